// round 16
// baseline (speedup 1.0000x reference)
#include <cuda_runtime.h>
#include <cuda_bf16.h>
#include <cuda_fp16.h>
#include <math.h>

// Problem constants
#define BB 2
#define SS 2048
#define DIMV 2048
#define HH 16
#define DHD 128
#define FFV 8192
#define MROWS (BB*SS)          // 4096

#if defined(__CUDA_ARCH_FEAT_SM103_ALL) || defined(__CUDA_ARCH_FEAT_SM100_ALL) || defined(__CUDA_ARCH_SPECIFIC__)
#define HAS_TCGEN05 1
#else
#define HAS_TCGEN05 0
#endif

// ---------------- scratch (device globals, no allocation) ----------------
__device__ float g_n [(size_t)MROWS*DIMV];
__device__ float g_q [(size_t)MROWS*DIMV];
__device__ float g_k [(size_t)MROWS*DIMV];
__device__ float g_v [(size_t)MROWS*DIMV];
__device__ float g_qt[(size_t)MROWS*DIMV];   // fallback fp32 q
__device__ float g_kt[(size_t)MROWS*DIMV];   // fallback fp32 k
__device__ float g_vt[(size_t)MROWS*DIMV];   // fallback fp32 v
__device__ float g_h [(size_t)MROWS*FFV];

// fp16 activations
__device__ unsigned short g_ah[(size_t)MROWS*DIMV];
__device__ unsigned short g_hh[(size_t)MROWS*FFV];   // also staging for fp16 q/k/v

// fp16 q/k/v for tensor attention  [b,h,s,dh]; v^T [b,h,dh,s]
__device__ unsigned short g_qth[(size_t)MROWS*DIMV];
__device__ unsigned short g_kth[(size_t)MROWS*DIMV];
__device__ unsigned short g_vth[(size_t)MROWS*DIMV];
__device__ unsigned short g_vtth[(size_t)MROWS*DIMV];

// fp16 transposed weights [N,K]
__device__ unsigned short g_wqh[(size_t)DIMV*DIMV];
__device__ unsigned short g_wkh[(size_t)DIMV*DIMV];
__device__ unsigned short g_wvh[(size_t)DIMV*DIMV];
__device__ unsigned short g_woh[(size_t)DIMV*DIMV];
__device__ unsigned short g_w1h[(size_t)DIMV*FFV];
__device__ unsigned short g_w2h[(size_t)DIMV*FFV];

// ---------------- f32x2 helpers (fallback paths) ----------------
__device__ __forceinline__ unsigned long long f2pack(float lo, float hi){
    unsigned long long r;
    asm("mov.b64 %0, {%1, %2};" : "=l"(r) : "f"(lo), "f"(hi));
    return r;
}
__device__ __forceinline__ unsigned long long f2dup(float x){
    unsigned long long r;
    asm("mov.b64 %0, {%1, %1};" : "=l"(r) : "f"(x));
    return r;
}
__device__ __forceinline__ unsigned long long f2fma(unsigned long long a, unsigned long long b, unsigned long long c){
    unsigned long long d;
    asm("fma.rn.f32x2 %0, %1, %2, %3;" : "=l"(d) : "l"(a), "l"(b), "l"(c));
    return d;
}
__device__ __forceinline__ unsigned long long f2mul(unsigned long long a, unsigned long long b){
    unsigned long long d;
    asm("mul.rn.f32x2 %0, %1, %2;" : "=l"(d) : "l"(a), "l"(b));
    return d;
}
__device__ __forceinline__ float2 f2unpack(unsigned long long v){
    float2 f;
    asm("mov.b64 {%0, %1}, %2;" : "=f"(f.x), "=f"(f.y) : "l"(v));
    return f;
}

// ---------------- fp16 pack helpers ----------------
__device__ __forceinline__ unsigned int cvt2h(float a, float b){
    __half2 h2 = __floats2half2_rn(a, b);
    return *(unsigned int*)&h2;
}
__device__ __forceinline__ void cvt_h_store(unsigned short* __restrict__ Ah,
                                            size_t idx, float4 v){
    uint2 hp;
    hp.x = cvt2h(v.x, v.y);
    hp.y = cvt2h(v.z, v.w);
    *(uint2*)(Ah + idx) = hp;
}
__device__ __forceinline__ void pack8_h(const float* v, uint4& hp){
    hp.x = cvt2h(v[0], v[1]);
    hp.y = cvt2h(v[2], v[3]);
    hp.z = cvt2h(v[4], v[5]);
    hp.w = cvt2h(v[6], v[7]);
}
__device__ __forceinline__ float4 ld_h4(const unsigned short* __restrict__ Ah, size_t idx){
    uint2 hp = *(const uint2*)(Ah + idx);
    __half2 a = *(__half2*)&hp.x;
    __half2 b = *(__half2*)&hp.y;
    float2 fa = __half22float2(a);
    float2 fb = __half22float2(b);
    return make_float4(fa.x, fa.y, fb.x, fb.y);
}

// ---------------- reductions ----------------
__device__ __forceinline__ float blockSum256(float v, float* sred){
    #pragma unroll
    for (int o=16;o>0;o>>=1) v += __shfl_xor_sync(0xffffffffu, v, o);
    __syncthreads();
    if ((threadIdx.x & 31)==0) sred[threadIdx.x>>5] = v;
    __syncthreads();
    float r = 0.f;
    #pragma unroll
    for (int i=0;i<8;i++) r += sred[i];
    return r;
}
__device__ __forceinline__ float warpSum(float v){
    #pragma unroll
    for (int o=16;o>0;o>>=1) v += __shfl_xor_sync(0xffffffffu, v, o);
    return v;
}

// ---------------- LayerNorm over DIM=2048 (+ fused fp16; fp32 out elided on tcgen05) ----------------
__global__ void __launch_bounds__(256) ln_kernel(const float* __restrict__ x,
                                                 const float* __restrict__ w,
                                                 const float* __restrict__ bia,
                                                 float* __restrict__ out,
                                                 unsigned short* __restrict__ Ah){
    __shared__ float sred[8];
    const int row = blockIdx.x;
    const int t = threadIdx.x;
    const float* xr = x + (size_t)row*DIMV;
    float4 a = *(const float4*)&xr[t*4];
    float4 b = *(const float4*)&xr[1024 + t*4];
    float s = a.x+a.y+a.z+a.w + b.x+b.y+b.z+b.w;
    s = blockSum256(s, sred);
    float mean = s * (1.f/2048.f);
    float d0=a.x-mean,d1=a.y-mean,d2=a.z-mean,d3=a.w-mean;
    float d4=b.x-mean,d5=b.y-mean,d6=b.z-mean,d7=b.w-mean;
    float sq = d0*d0+d1*d1+d2*d2+d3*d3+d4*d4+d5*d5+d6*d6+d7*d7;
    sq = blockSum256(sq, sred);
    float inv = rsqrtf(sq*(1.f/2048.f) + 1e-5f);
    float4 w0 = *(const float4*)&w[t*4];
    float4 w1 = *(const float4*)&w[1024 + t*4];
    float4 b0 = *(const float4*)&bia[t*4];
    float4 b1 = *(const float4*)&bia[1024 + t*4];
    float4 o0 = make_float4(d0*inv*w0.x+b0.x, d1*inv*w0.y+b0.y, d2*inv*w0.z+b0.z, d3*inv*w0.w+b0.w);
    float4 o1 = make_float4(d4*inv*w1.x+b1.x, d5*inv*w1.y+b1.y, d6*inv*w1.z+b1.z, d7*inv*w1.w+b1.w);
#if HAS_TCGEN05
    cvt_h_store(Ah, (size_t)row*DIMV + t*4, o0);
    cvt_h_store(Ah, (size_t)row*DIMV + 1024 + t*4, o1);
#else
    float* orow = out + (size_t)row*DIMV;
    *(float4*)&orow[t*4] = o0;
    *(float4*)&orow[1024 + t*4] = o1;
#endif
}

// ---------------- weight transpose + fp16 ----------------
__global__ void __launch_bounds__(256) wconv_kernel(const float* __restrict__ W,
                                                    unsigned short* __restrict__ Wh,
                                                    int K, int N){
#if HAS_TCGEN05
    __shared__ float sm[32][33];
    const int n0 = blockIdx.x*32, k0 = blockIdx.y*32;
    const int tx = threadIdx.x & 31;
    const int ty = threadIdx.x >> 5;
    #pragma unroll
    for (int i=0;i<4;i++)
        sm[ty + i*8][tx] = W[(size_t)(k0 + ty + i*8)*N + n0 + tx];
    __syncthreads();
    #pragma unroll
    for (int i=0;i<4;i++){
        int nn = ty + i*8;
        float v = sm[tx][nn];
        __half h = __float2half_rn(v);
        Wh[(size_t)(n0+nn)*K + k0 + tx] = *(unsigned short*)&h;
    }
#endif
}

// ---------------- shared GEMM machinery ----------------
#define GBK 64
#define SW128(x) ((x) ^ (((x) >> 3) & 0x70))

static constexpr unsigned long long DESC_BASE =
    (2ull<<61) | (1ull<<46) | (64ull<<32) | (1ull<<16);   // SW128, ver1, SBO=64, LBO=1
__device__ __forceinline__ unsigned long long mkdesc(unsigned int addr){
    return DESC_BASE | ((unsigned long long)(addr >> 4) & 0x3FFFull);
}
#define IDESC_F16 ((1u<<4)|(16u<<17)|(8u<<24))   // M=128, N=128
#define IDESC_S16 ((1u<<4)|(8u<<17) |(8u<<24))   // M=128, N=64

__device__ __forceinline__ unsigned int smem_u32(const void* p){
    unsigned int a;
    asm("{ .reg .u64 t; cvta.to.shared.u64 t, %1; cvt.u32.u64 %0, t; }" : "=r"(a) : "l"(p));
    return a;
}

#if HAS_TCGEN05
__device__ __forceinline__ unsigned int elect1(){
    unsigned int p;
    asm volatile("{ .reg .pred P; elect.sync _|P, 0xffffffff; selp.b32 %0, 1, 0, P; }" : "=r"(p));
    return p;
}
__device__ __forceinline__ void mbar_init(unsigned int a, unsigned int cnt){
    asm volatile("mbarrier.init.shared.b64 [%0], %1;" :: "r"(a), "r"(cnt) : "memory");
}
__device__ __forceinline__ void mbar_wait(unsigned int a, unsigned int parity){
    asm volatile("{ .reg .pred P; WL_%=: mbarrier.try_wait.parity.shared.b64 P, [%0], %1; @!P bra WL_%=; }"
        :: "r"(a), "r"(parity) : "memory");
}
__device__ __forceinline__ void mma_f16_ss(unsigned int d, unsigned long long ad,
                                           unsigned long long bd, unsigned int idesc,
                                           unsigned int en){
    asm volatile("{\n\t.reg .pred p;\n\tsetp.ne.u32 p, %4, 0;\n\t"
        "tcgen05.mma.cta_group::1.kind::f16 [%0], %1, %2, %3, {%5,%5,%5,%5}, p;\n\t}"
        :: "r"(d), "l"(ad), "l"(bd), "r"(idesc), "r"(en), "r"(0u) : "memory");
}
__device__ __forceinline__ void tc_commit(unsigned int mbar){
    asm volatile("tcgen05.commit.cta_group::1.mbarrier::arrive::one.shared::cluster.b64 [%0];"
        :: "r"(mbar) : "memory");
}
// cp.async 16B (LDGSTS)
__device__ __forceinline__ void cp16(unsigned int dst, const void* src){
    asm volatile("cp.async.cg.shared.global [%0], [%1], 16;" :: "r"(dst), "l"(src) : "memory");
}
#define CP_COMMIT() asm volatile("cp.async.commit_group;" ::: "memory")
#define CP_WAIT0()  asm volatile("cp.async.wait_group 0;" ::: "memory")
#define CP_WAIT2()  asm volatile("cp.async.wait_group 2;" ::: "memory")
#define LDTM_X32(r, addr) \
    asm volatile("tcgen05.ld.sync.aligned.32x32b.x32.b32 " \
        "{%0, %1, %2, %3, %4, %5, %6, %7, %8, %9, %10, %11, %12, %13, %14, %15, " \
        " %16, %17, %18, %19, %20, %21, %22, %23, %24, %25, %26, %27, %28, %29, %30, %31}, [%32];" \
        : "=r"((r)[0]),  "=r"((r)[1]),  "=r"((r)[2]),  "=r"((r)[3]), \
          "=r"((r)[4]),  "=r"((r)[5]),  "=r"((r)[6]),  "=r"((r)[7]), \
          "=r"((r)[8]),  "=r"((r)[9]),  "=r"((r)[10]), "=r"((r)[11]), \
          "=r"((r)[12]), "=r"((r)[13]), "=r"((r)[14]), "=r"((r)[15]), \
          "=r"((r)[16]), "=r"((r)[17]), "=r"((r)[18]), "=r"((r)[19]), \
          "=r"((r)[20]), "=r"((r)[21]), "=r"((r)[22]), "=r"((r)[23]), \
          "=r"((r)[24]), "=r"((r)[25]), "=r"((r)[26]), "=r"((r)[27]), \
          "=r"((r)[28]), "=r"((r)[29]), "=r"((r)[30]), "=r"((r)[31]) \
        : "r"(addr))
#endif

// ---------------- tgemm: 128x128 tiles, 3-stage cp.async pipeline (2 CTAs/SM) ----------------
#define NST 3
#define STAGE_BYTES 32768                 // Ah 16K | Bh 16K
#define SM_MBAR_OFF (NST*STAGE_BYTES)
#define SM_TPTR_OFF (SM_MBAR_OFF + 64)
#define GEMM_SMEM   (SM_TPTR_OFF + 64)

__global__ void __launch_bounds__(256) tgemm_kernel(const float* __restrict__ A,
        const unsigned short* __restrict__ Ah,
        const unsigned short* __restrict__ Bh,
        const float* __restrict__ Wf,
        const float* __restrict__ bias, const float* __restrict__ res,
        float* __restrict__ C,
        unsigned short* __restrict__ Cho,
        int M, int N, int K, int epi, int cvt, int wrC){
    extern __shared__ __align__(1024) char smem[];
    const int tid = threadIdx.x;
    const int n0 = blockIdx.x*128, m0 = blockIdx.y*128;

#if HAS_TCGEN05
    const unsigned int sb = smem_u32(smem);
    const int wid = tid >> 5, lid = tid & 31;

    if (wid == 0){
        asm volatile("tcgen05.alloc.cta_group::1.sync.aligned.shared::cta.b32 [%0], %1;"
            :: "r"(sb + SM_TPTR_OFF), "r"(128u) : "memory");
    }
    if (tid == 0){
        #pragma unroll
        for (int s=0;s<NST;s++) mbar_init(sb + SM_MBAR_OFF + s*8, 1);
    }
    __syncthreads();
    unsigned int tmem;
    asm volatile("ld.shared.b32 %0, [%1];" : "=r"(tmem) : "r"(sb + SM_TPTR_OFF));

    unsigned int pha[NST];
    #pragma unroll
    for (int s=0;s<NST;s++) pha[s]=0u;
    const int T = K / GBK;

    // prologue: tiles 0..1 -> stages 0..1 (one cp group per tile)
    #pragma unroll
    for (int p=0;p<2;p++){
        const unsigned int stp = sb + p*STAGE_BYTES;
        const int kp = p*GBK;
        #pragma unroll
        for (int i=0;i<4;i++){
            int ch = tid + i*256;
            int r = ch >> 3, cc = ch & 7;
            unsigned int sw = SW128((unsigned)(r*128 + cc*16));
            cp16(stp + 0     + sw, Ah + (size_t)(m0+r)*K + kp + cc*8);
            cp16(stp + 16384 + sw, Bh + (size_t)(n0+r)*K + kp + cc*8);
        }
        CP_COMMIT();
    }

    for (int t=0; t<T; t++){
        const int s = t % NST;
        const unsigned int stb = sb + s*STAGE_BYTES;
        if (t + 2 < T){
            const int ds = (t+2) % NST;    // stage for tile t+2 (== stage of tile t-1)
            if (t >= 1){
                mbar_wait(sb + SM_MBAR_OFF + ds*8, pha[ds]);
                pha[ds] ^= 1u;
            }
            const int k1 = (t+2)*GBK;
            const unsigned int stn = sb + ds*STAGE_BYTES;
            #pragma unroll
            for (int i=0;i<4;i++){
                int ch = tid + i*256;
                int r = ch >> 3, cc = ch & 7;
                unsigned int sw = SW128((unsigned)(r*128 + cc*16));
                cp16(stn + 0     + sw, Ah + (size_t)(m0+r)*K + k1 + cc*8);
                cp16(stn + 16384 + sw, Bh + (size_t)(n0+r)*K + k1 + cc*8);
            }
            CP_COMMIT();
            CP_WAIT2();          // tile t complete; t+1,t+2 in flight
        } else {
            CP_WAIT0();
        }
        asm volatile("fence.proxy.async.shared::cta;" ::: "memory");
        __syncthreads();
        if (wid == 0 && elect1()){
            unsigned long long dah = mkdesc(stb + 0);
            unsigned long long dbh = mkdesc(stb + 16384);
            unsigned int en0 = (t > 0) ? 1u : 0u;
            #pragma unroll
            for (int ks=0; ks<4; ks++)
                mma_f16_ss(tmem, dah + ks*2, dbh + ks*2, IDESC_F16, (ks==0)?en0:1u);
            tc_commit(sb + SM_MBAR_OFF + s*8);
        }
    }
    #pragma unroll
    for (int s=0;s<NST;s++) mbar_wait(sb + SM_MBAR_OFF + s*8, pha[s]);
    asm volatile("tcgen05.fence::after_thread_sync;" ::: "memory");

    if (wid < 4){
        const int m = m0 + wid*32 + lid;
        float* crow = C + (size_t)m*N + n0;
        #pragma unroll
        for (int c0=0; c0<128; c0+=32){
            unsigned int r[32];
            LDTM_X32(r, tmem + c0);
            asm volatile("tcgen05.wait::ld.sync.aligned;" ::: "memory");
            float vals[32];
            #pragma unroll
            for (int j=0;j<32;j++){
                float v = __uint_as_float(r[j]);
                int n = n0 + c0 + j;
                if (epi >= 1) v += bias[n];
                if (epi == 2) v = 0.5f * v * (1.0f + erff(v * 0.70710678118654752f));
                if (epi == 3) v += res[(size_t)m*N + n];
                vals[j] = v;
            }
            #pragma unroll
            for (int j=0;j<32;j+=4){
                float4 o4 = make_float4(vals[j],vals[j+1],vals[j+2],vals[j+3]);
                if (wrC) *(float4*)&crow[c0 + j] = o4;
                if (cvt) cvt_h_store(Cho, (size_t)m*N + n0 + c0 + j, o4);
            }
        }
    }
    __syncthreads();
    if (tid == 0){
        #pragma unroll
        for (int s=0;s<NST;s++)
            asm volatile("mbarrier.inval.shared.b64 [%0];" :: "r"(sb + SM_MBAR_OFF + s*8) : "memory");
    }
    __syncthreads();
    if (wid == 0){
        asm volatile("tcgen05.dealloc.cta_group::1.sync.aligned.b32 %0, %1;" :: "r"(tmem), "r"(128u));
    }

#else
    // fallback: fp32 SIMT f32x2 GEMM (R1-proven)
    float* As = (float*)smem;
    float* Bs = As + 16*128;
    const int tx = tid & 15;
    const int ty = tid >> 4;
    const float* Ab = A  + (size_t)m0*K;
    const float* Bb = Wf + n0;

    unsigned long long accp[8][4];
    #pragma unroll
    for (int i=0;i<8;i++)
        #pragma unroll
        for (int j=0;j<4;j++) accp[i][j] = 0ull;

    for (int k0=0; k0<K; k0+=16){
        #pragma unroll
        for (int l=0;l<2;l++){
            int f = tid + l*256;
            int r = f >> 2;
            int c4 = (f & 3) << 2;
            float4 v = *(const float4*)(Ab + (size_t)r*K + k0 + c4);
            As[(c4+0)*128+r]=v.x; As[(c4+1)*128+r]=v.y; As[(c4+2)*128+r]=v.z; As[(c4+3)*128+r]=v.w;
        }
        #pragma unroll
        for (int l=0;l<2;l++){
            int f = tid + l*256;
            int r = f >> 5;
            int c = (f & 31) << 2;
            *(float4*)(&Bs[r*128+c]) = *(const float4*)(Bb + (size_t)(k0+r)*N + c);
        }
        __syncthreads();
        #pragma unroll
        for (int kk=0;kk<16;kk++){
            float4 a0 = *(const float4*)(&As[kk*128 + ty*4]);
            float4 a1 = *(const float4*)(&As[kk*128 + ty*4+64]);
            float4 b0 = *(const float4*)(&Bs[kk*128 + tx*4]);
            float4 b1 = *(const float4*)(&Bs[kk*128 + tx*4+64]);
            unsigned long long bp0 = f2pack(b0.x,b0.y);
            unsigned long long bp1 = f2pack(b0.z,b0.w);
            unsigned long long bp2 = f2pack(b1.x,b1.y);
            unsigned long long bp3 = f2pack(b1.z,b1.w);
            float av[8] = {a0.x,a0.y,a0.z,a0.w,a1.x,a1.y,a1.z,a1.w};
            #pragma unroll
            for (int i=0;i<8;i++){
                unsigned long long ad = f2dup(av[i]);
                accp[i][0] = f2fma(ad, bp0, accp[i][0]);
                accp[i][1] = f2fma(ad, bp1, accp[i][1]);
                accp[i][2] = f2fma(ad, bp2, accp[i][2]);
                accp[i][3] = f2fma(ad, bp3, accp[i][3]);
            }
        }
        __syncthreads();
    }

    const int row0 = m0 + ty*4;
    const int col0 = n0 + tx*4;
    #pragma unroll
    for (int i=0;i<8;i++){
        int r = row0 + ((i<4) ? i : (60+i));
        float2 u0 = f2unpack(accp[i][0]);
        float2 u1 = f2unpack(accp[i][1]);
        float2 u2 = f2unpack(accp[i][2]);
        float2 u3 = f2unpack(accp[i][3]);
        float vals[8] = {u0.x,u0.y,u1.x,u1.y,u2.x,u2.y,u3.x,u3.y};
        float outv[8];
        #pragma unroll
        for (int jj=0;jj<8;jj++){
            int c = col0 + ((jj<4) ? jj : (60+jj));
            float v = vals[jj];
            if (epi >= 1) v += bias[c];
            if (epi == 2) v = 0.5f * v * (1.0f + erff(v * 0.70710678118654752f));
            if (epi == 3) v += res[(size_t)r*N + c];
            outv[jj] = v;
        }
        float* crow = C + (size_t)r*N;
        *(float4*)&crow[col0]      = make_float4(outv[0],outv[1],outv[2],outv[3]);
        *(float4*)&crow[col0 + 64] = make_float4(outv[4],outv[5],outv[6],outv[7]);
    }
#endif
}

// ---------------- per-head LN + rotary + transpose ----------------
__global__ void __launch_bounds__(256) qkrot_kernel(const float* __restrict__ q,
                                                    const float* __restrict__ k,
                                                    const float* __restrict__ v,
                                                    const unsigned short* __restrict__ q16,
                                                    const unsigned short* __restrict__ k16,
                                                    const unsigned short* __restrict__ v16,
                                                    const float* __restrict__ nqw, const float* __restrict__ nqb,
                                                    const float* __restrict__ nkw, const float* __restrict__ nkb,
                                                    const float* __restrict__ fcos, const float* __restrict__ fsin,
                                                    float* __restrict__ qt, float* __restrict__ kt, float* __restrict__ vt,
                                                    unsigned short* __restrict__ qth,
                                                    unsigned short* __restrict__ kth,
                                                    unsigned short* __restrict__ vth){
    const int bs = blockIdx.x;
    const int b = bs >> 11;
    const int s = bs & (SS-1);
    const int wid = threadIdx.x >> 5;
    const int lane = threadIdx.x & 31;
    const int d0 = lane*4;
    const float c0 = fcos[s*64 + lane*2],     c1 = fcos[s*64 + lane*2 + 1];
    const float s0 = fsin[s*64 + lane*2],     s1 = fsin[s*64 + lane*2 + 1];
    const float4 wq4 = *(const float4*)&nqw[d0];
    const float4 bq4 = *(const float4*)&nqb[d0];
    const float4 wk4 = *(const float4*)&nkw[d0];
    const float4 bk4 = *(const float4*)&nkb[d0];
    const float scale = 0.08838834764831845f;
    #pragma unroll
    for (int hh = wid; hh < HH; hh += 8){
        size_t src = (size_t)bs*DIMV + hh*DHD + d0;
        size_t dst = ((size_t)(b*HH + hh)*SS + s)*DHD + d0;
        {
#if HAS_TCGEN05
            float4 xv = ld_h4(q16, src);
#else
            float4 xv = *(const float4*)&q[src];
#endif
            float mean = warpSum(xv.x+xv.y+xv.z+xv.w) * (1.f/128.f);
            float e0=xv.x-mean, e1=xv.y-mean, e2=xv.z-mean, e3=xv.w-mean;
            float var = warpSum(e0*e0+e1*e1+e2*e2+e3*e3) * (1.f/128.f);
            float inv = rsqrtf(var + 1e-5f);
            float y0 = e0*inv*wq4.x + bq4.x;
            float y1 = e1*inv*wq4.y + bq4.y;
            float y2 = e2*inv*wq4.z + bq4.z;
            float y3 = e3*inv*wq4.w + bq4.w;
            float4 r4 = make_float4(y0*c0 - y1*s0, y0*s0 + y1*c0,
                                    y2*c1 - y3*s1, y2*s1 + y3*c1);
#if HAS_TCGEN05
            float4 rs = make_float4(r4.x*scale, r4.y*scale, r4.z*scale, r4.w*scale);
            cvt_h_store(qth, dst, rs);
#else
            *(float4*)&qt[dst] = r4;
#endif
        }
        {
#if HAS_TCGEN05
            float4 xv = ld_h4(k16, src);
#else
            float4 xv = *(const float4*)&k[src];
#endif
            float mean = warpSum(xv.x+xv.y+xv.z+xv.w) * (1.f/128.f);
            float e0=xv.x-mean, e1=xv.y-mean, e2=xv.z-mean, e3=xv.w-mean;
            float var = warpSum(e0*e0+e1*e1+e2*e2+e3*e3) * (1.f/128.f);
            float inv = rsqrtf(var + 1e-5f);
            float y0 = e0*inv*wk4.x + bk4.x;
            float y1 = e1*inv*wk4.y + bk4.y;
            float y2 = e2*inv*wk4.z + bk4.z;
            float y3 = e3*inv*wk4.w + bk4.w;
            float4 r4 = make_float4(y0*c0 - y1*s0, y0*s0 + y1*c0,
                                    y2*c1 - y3*s1, y2*s1 + y3*c1);
#if HAS_TCGEN05
            cvt_h_store(kth, dst, r4);
#else
            *(float4*)&kt[dst] = r4;
#endif
        }
        {
#if HAS_TCGEN05
            uint2 hp = *(const uint2*)(v16 + src);
            *(uint2*)(vth + dst) = hp;
#else
            float4 xv = *(const float4*)&v[src];
            *(float4*)&vt[dst] = xv;
#endif
        }
    }
}

// ---------------- V transpose: [b,h,s,dh] -> [b,h,dh,s] ----------------
__global__ void __launch_bounds__(256) vtrans_kernel(const unsigned short* __restrict__ Vh,
                                                     unsigned short* __restrict__ Vth){
#if HAS_TCGEN05
    __shared__ unsigned short smh[32][33];
    const int s0 = blockIdx.x*32;
    const int d0 = blockIdx.y*32;
    const int bh = blockIdx.z;
    const int tx = threadIdx.x & 31;
    const int ty = threadIdx.x >> 5;
    const size_t inb  = (size_t)bh*SS*DHD + (size_t)s0*DHD + d0;
    const size_t outb = (size_t)bh*DHD*SS + (size_t)d0*SS + s0;
    #pragma unroll
    for (int i=0;i<4;i++){
        int r = ty + i*8;
        smh[r][tx] = Vh[inb + (size_t)r*DHD + tx];
    }
    __syncthreads();
    #pragma unroll
    for (int i=0;i<4;i++){
        int r = ty + i*8;
        Vth[outb + (size_t)r*SS + tx] = smh[tx][r];
    }
#endif
}

// ---------------- attention (fp16; double-buffered cp.async K/V) ----------------
#define AQ_H 0          // 32KB (2 dh-half blocks)
#define AK0  32768      // 16KB
#define AK1  49152
#define AV0  65536      // 16KB
#define AV1  81920
#define AP_H 98304      // 16KB
#define A_MBAR 114688
#define A_TPTR 114752
#define AT_SMEM 114816

__global__ void __launch_bounds__(256) attn_kernel(const float* __restrict__ Qf,
                                                   const float* __restrict__ Kf,
                                                   const float* __restrict__ Vf,
                                                   const unsigned short* __restrict__ Qh,
                                                   const unsigned short* __restrict__ Kh,
                                                   const unsigned short* __restrict__ Vth,
                                                   float* __restrict__ O,
                                                   unsigned short* __restrict__ Oh){
    extern __shared__ __align__(1024) char smem[];
#if HAS_TCGEN05
    const unsigned int sb = smem_u32(smem);
    const int tid = threadIdx.x;
    const int wid = tid >> 5, lid = tid & 31;
    const int q0 = blockIdx.x * 128;
    const int bh = blockIdx.y;
    const int b = bh >> 4, h = bh & 15;
    const size_t base  = (size_t)bh * SS * DHD;
    const size_t baseT = (size_t)bh * DHD * SS;
    const unsigned int AKo[2] = {AK0, AK1};
    const unsigned int AVo[2] = {AV0, AV1};

    if (wid == 0){
        asm volatile("tcgen05.alloc.cta_group::1.sync.aligned.shared::cta.b32 [%0], %1;"
            :: "r"(sb + A_TPTR), "r"(256u) : "memory");
    }
    if (tid == 0) mbar_init(sb + A_MBAR, 1);
    __syncthreads();
    unsigned int tmem;
    asm volatile("ld.shared.b32 %0, [%1];" : "=r"(tmem) : "r"(sb + A_TPTR));

    // Q tile (cp.async)
    #pragma unroll
    for (int i=0;i<8;i++){
        int ch = tid + i*256;
        int r = ch >> 4, c = ch & 15;
        int blk = c >> 3;
        unsigned int sw = blk*16384 + SW128((unsigned)(r*128 + (c&7)*16));
        cp16(sb + AQ_H + sw, Qh + base + (size_t)(q0+r)*DHD + c*8);
    }
    // prologue: K/V block 0 into buf0 (cp.async)
    #pragma unroll
    for (int i=0;i<4;i++){
        int ch = tid + i*256;
        int r = ch >> 4, c = ch & 15;
        int blk = c >> 3;
        unsigned int sw = blk*8192 + SW128((unsigned)(r*128 + (c&7)*16));
        cp16(sb + AK0 + sw, Kh + base + (size_t)r*DHD + c*8);
    }
    #pragma unroll
    for (int i=0;i<4;i++){
        int ch = tid + i*256;
        int r = ch >> 3, c = ch & 7;
        unsigned int sw = SW128((unsigned)(r*128 + c*16));
        cp16(sb + AV0 + sw, Vth + baseT + (size_t)r*SS + c*8);
    }
    CP_COMMIT();
    CP_WAIT0();
    asm volatile("fence.proxy.async.shared::cta;" ::: "memory");
    __syncthreads();

    float lsum = 0.f;
    unsigned int ph = 0u;
    const int NKB = SS/64;

    for (int kb = 0; kb < NKB; kb++){
        const int cur = kb & 1;
        const int nxt = cur ^ 1;

        // S = Q K^T from buf cur
        if (wid == 0 && elect1()){
            #pragma unroll
            for (int blk=0; blk<2; blk++){
                unsigned long long da = mkdesc(sb + AQ_H + blk*16384);
                unsigned long long db = mkdesc(sb + AKo[cur] + blk*8192);
                #pragma unroll
                for (int ks=0; ks<4; ks++){
                    unsigned int en = (blk==0 && ks==0) ? 0u : 1u;
                    mma_f16_ss(tmem, da + ks*2, db + ks*2, IDESC_S16, en);
                }
            }
            tc_commit(sb + A_MBAR);
        }

        // prefetch K/V block kb+1 into buf nxt (cp.async, overlaps S-MMA)
        if (kb + 1 < NKB){
            const int k1 = (kb+1)*64;
            #pragma unroll
            for (int i=0;i<4;i++){
                int ch = tid + i*256;
                int r = ch >> 4, c = ch & 15;
                int blk = c >> 3;
                unsigned int sw = blk*8192 + SW128((unsigned)(r*128 + (c&7)*16));
                cp16(sb + AKo[nxt] + sw, Kh + base + (size_t)(k1+r)*DHD + c*8);
            }
            #pragma unroll
            for (int i=0;i<4;i++){
                int ch = tid + i*256;
                int r = ch >> 3, c = ch & 7;
                unsigned int sw = SW128((unsigned)(r*128 + c*16));
                cp16(sb + AVo[nxt] + sw, Vth + baseT + (size_t)r*SS + k1 + c*8);
            }
            CP_COMMIT();
        }

        mbar_wait(sb + A_MBAR, ph); ph ^= 1u;
        asm volatile("tcgen05.fence::after_thread_sync;" ::: "memory");

        // softmax (no max-subtraction) + P fp16 store
        if (wid < 4){
            const int r = wid*32 + lid;
            #pragma unroll
            for (int c0=0; c0<64; c0+=32){
                unsigned int sr[32];
                LDTM_X32(sr, tmem + c0);
                asm volatile("tcgen05.wait::ld.sync.aligned;" ::: "memory");
                float pv[32];
                #pragma unroll
                for (int j=0;j<32;j++){
                    float e = __expf(fminf(__uint_as_float(sr[j]), 10.f));
                    pv[j] = e;
                    lsum += e;
                }
                #pragma unroll
                for (int j0=0;j0<32;j0+=8){
                    uint4 hp;
                    pack8_h(&pv[j0], hp);
                    unsigned int sw = SW128((unsigned)(r*128 + (c0+j0)*2));
                    *(uint4*)(smem + AP_H + sw) = hp;
                }
            }
        }
        // wait prefetch + fence + sync cover P stores AND nxt K/V
        CP_WAIT0();
        asm volatile("fence.proxy.async.shared::cta;" ::: "memory");
        __syncthreads();

        // O += P V from buf cur
        if (wid == 0 && elect1()){
            unsigned long long da = mkdesc(sb + AP_H);
            unsigned long long db = mkdesc(sb + AVo[cur]);
            #pragma unroll
            for (int ks=0; ks<4; ks++){
                unsigned int en = (kb==0 && ks==0) ? 0u : 1u;
                mma_f16_ss(tmem + 64, da + ks*2, db + ks*2, IDESC_F16, en);
            }
            tc_commit(sb + A_MBAR);
        }
        mbar_wait(sb + A_MBAR, ph); ph ^= 1u;
        asm volatile("tcgen05.fence::after_thread_sync;" ::: "memory");
    }

    // epilogue: normalize, write fp16 O
    if (wid < 4){
        const int r = wid*32 + lid;
        const float invl = 1.f / lsum;
        const size_t obase = (size_t)(b*SS + q0 + r)*DIMV + h*DHD;
        #pragma unroll
        for (int c0=0; c0<128; c0+=32){
            unsigned int orr[32];
            LDTM_X32(orr, tmem + 64 + c0);
            asm volatile("tcgen05.wait::ld.sync.aligned;" ::: "memory");
            #pragma unroll
            for (int j=0;j<32;j+=4){
                float4 o4 = make_float4(__uint_as_float(orr[j+0])*invl,
                                        __uint_as_float(orr[j+1])*invl,
                                        __uint_as_float(orr[j+2])*invl,
                                        __uint_as_float(orr[j+3])*invl);
                cvt_h_store(Oh, obase + c0 + j, o4);
            }
        }
    }
    __syncthreads();
    if (tid == 0){
        asm volatile("mbarrier.inval.shared.b64 [%0];" :: "r"(sb + A_MBAR) : "memory");
    }
    __syncthreads();
    if (wid == 0){
        asm volatile("tcgen05.dealloc.cta_group::1.sync.aligned.b32 %0, %1;" :: "r"(tmem), "r"(256u));
    }

#else
    // fallback: R5-proven SIMT attention, two 64-row halves
    float* smf = (float*)smem;
    #define QS_LD 68
    #define PS_LD 65
    float* Qs = smf;
    float* Ks = Qs + 128*QS_LD;
    float* Vs = Ks + 128*QS_LD;
    float* Ps = Vs + 64*128;
    const int bh = blockIdx.y;
    const int b = bh >> 4, h = bh & 15;
    const size_t base = (size_t)bh * SS * DHD;
    const int tid = threadIdx.x;
    const int tx = tid & 15;
    const int ty = tid >> 4;
    const float scale = 0.08838834764831845f;

    for (int qh = 0; qh < 2; qh++){
        const int q0 = blockIdx.x * 128 + qh*64;
        __syncthreads();
        for (int t=tid; t<64*128; t+=256){
            int r = t >> 7, d = t & 127;
            Qs[d*QS_LD + r] = Qf[base + (size_t)(q0+r)*DHD + d] * scale;
        }

        float m[4], l[4];
        unsigned long long o2[4][4];
        #pragma unroll
        for (int i=0;i<4;i++){
            m[i] = -1e30f; l[i] = 0.f;
            #pragma unroll
            for (int j=0;j<4;j++) o2[i][j] = 0ull;
        }

        for (int k0=0; k0<SS; k0+=64){
            __syncthreads();
            for (int t=tid; t<64*128; t+=256){
                int r = t >> 7, d = t & 127;
                Ks[d*QS_LD + r] = Kf[base + (size_t)(k0+r)*DHD + d];
                Vs[t]           = Vf[base + (size_t)(k0+r)*DHD + d];
            }
            __syncthreads();

            unsigned long long s2[4][2];
            #pragma unroll
            for (int i=0;i<4;i++){ s2[i][0]=0ull; s2[i][1]=0ull; }
            #pragma unroll 4
            for (int d=0; d<128; d++){
                float4 qv = *(const float4*)&Qs[d*QS_LD + ty*4];
                float4 kv = *(const float4*)&Ks[d*QS_LD + tx*4];
                unsigned long long kp0 = f2pack(kv.x,kv.y);
                unsigned long long kp1 = f2pack(kv.z,kv.w);
                float qa[4] = {qv.x,qv.y,qv.z,qv.w};
                #pragma unroll
                for (int i=0;i<4;i++){
                    unsigned long long qd = f2dup(qa[i]);
                    s2[i][0] = f2fma(qd, kp0, s2[i][0]);
                    s2[i][1] = f2fma(qd, kp1, s2[i][1]);
                }
            }

            #pragma unroll
            for (int i=0;i<4;i++){
                float2 sa = f2unpack(s2[i][0]);
                float2 sb2 = f2unpack(s2[i][1]);
                float sv0=sa.x, sv1=sa.y, sv2=sb2.x, sv3=sb2.y;
                float mt = fmaxf(fmaxf(sv0,sv1), fmaxf(sv2,sv3));
                #pragma unroll
                for (int o=1;o<16;o<<=1) mt = fmaxf(mt, __shfl_xor_sync(0xffffffffu, mt, o));
                float mnew = fmaxf(m[i], mt);
                float alpha = __expf(m[i] - mnew);
                float p0 = __expf(sv0 - mnew);
                float p1 = __expf(sv1 - mnew);
                float p2 = __expf(sv2 - mnew);
                float p3 = __expf(sv3 - mnew);
                float ssum = p0+p1+p2+p3;
                #pragma unroll
                for (int o=1;o<16;o<<=1) ssum += __shfl_xor_sync(0xffffffffu, ssum, o);
                l[i] = l[i]*alpha + ssum;
                m[i] = mnew;
                unsigned long long ad = f2dup(alpha);
                #pragma unroll
                for (int j=0;j<4;j++) o2[i][j] = f2mul(o2[i][j], ad);
                float* pr = &Ps[(ty*4+i)*PS_LD + tx*4];
                pr[0]=p0; pr[1]=p1; pr[2]=p2; pr[3]=p3;
            }
            __syncthreads();

            #pragma unroll 4
            for (int kk=0; kk<64; kk++){
                float4 v0 = *(const float4*)&Vs[kk*128 + tx*4];
                float4 v1 = *(const float4*)&Vs[kk*128 + 64 + tx*4];
                unsigned long long vp0 = f2pack(v0.x,v0.y);
                unsigned long long vp1 = f2pack(v0.z,v0.w);
                unsigned long long vp2 = f2pack(v1.x,v1.y);
                unsigned long long vp3 = f2pack(v1.z,v1.w);
                #pragma unroll
                for (int i=0;i<4;i++){
                    unsigned long long pd = f2dup(Ps[(ty*4+i)*PS_LD + kk]);
                    o2[i][0] = f2fma(pd, vp0, o2[i][0]);
                    o2[i][1] = f2fma(pd, vp1, o2[i][1]);
                    o2[i][2] = f2fma(pd, vp2, o2[i][2]);
                    o2[i][3] = f2fma(pd, vp3, o2[i][3]);
                }
            }
        }

        #pragma unroll
        for (int i=0;i<4;i++){
            float inv = 1.f / l[i];
            int r = q0 + ty*4 + i;
            size_t obase = (size_t)(b*SS + r)*DIMV + h*DHD;
            float2 p0 = f2unpack(o2[i][0]);
            float2 p1 = f2unpack(o2[i][1]);
            float2 p2 = f2unpack(o2[i][2]);
            float2 p3 = f2unpack(o2[i][3]);
            *(float4*)&O[obase + tx*4]      = make_float4(p0.x*inv, p0.y*inv, p1.x*inv, p1.y*inv);
            *(float4*)&O[obase + 64 + tx*4] = make_float4(p2.x*inv, p2.y*inv, p3.x*inv, p3.y*inv);
        }
    }
#endif
}

// ---------------- launch ----------------
extern "C" void kernel_launch(void* const* d_in, const int* in_sizes, int n_in,
                              void* d_out, int out_size){
    const float* x    = (const float*)d_in[0];
    const float* fcos = (const float*)d_in[1];
    const float* fsin = (const float*)d_in[2];
    const float* wq   = (const float*)d_in[3];
    const float* wk   = (const float*)d_in[4];
    const float* wv   = (const float*)d_in[5];
    const float* nqw  = (const float*)d_in[6];
    const float* nqb  = (const float*)d_in[7];
    const float* nkw  = (const float*)d_in[8];
    const float* nkb  = (const float*)d_in[9];
    const float* wo   = (const float*)d_in[10];
    const float* bo   = (const float*)d_in[11];
    const float* ln1w = (const float*)d_in[12];
    const float* ln1b = (const float*)d_in[13];
    const float* ln3w = (const float*)d_in[14];
    const float* ln3b = (const float*)d_in[15];
    const float* w1   = (const float*)d_in[16];
    const float* b1   = (const float*)d_in[17];
    const float* w2   = (const float*)d_in[18];
    const float* b2   = (const float*)d_in[19];
    float* out = (float*)d_out;

    float *n_, *q_, *k_, *v_, *qt_, *kt_, *vt_, *h_;
    cudaGetSymbolAddress((void**)&n_,  g_n);
    cudaGetSymbolAddress((void**)&q_,  g_q);
    cudaGetSymbolAddress((void**)&k_,  g_k);
    cudaGetSymbolAddress((void**)&v_,  g_v);
    cudaGetSymbolAddress((void**)&qt_, g_qt);
    cudaGetSymbolAddress((void**)&kt_, g_kt);
    cudaGetSymbolAddress((void**)&vt_, g_vt);
    cudaGetSymbolAddress((void**)&h_,  g_h);

    unsigned short *ah,*hh;
    cudaGetSymbolAddress((void**)&ah, g_ah);
    cudaGetSymbolAddress((void**)&hh, g_hh);
    unsigned short *q16 = hh;
    unsigned short *k16 = hh + (size_t)MROWS*DIMV;
    unsigned short *v16 = hh + 2*(size_t)MROWS*DIMV;

    unsigned short *qth,*kth,*vth,*vtth;
    cudaGetSymbolAddress((void**)&qth, g_qth);
    cudaGetSymbolAddress((void**)&kth, g_kth);
    cudaGetSymbolAddress((void**)&vth, g_vth);
    cudaGetSymbolAddress((void**)&vtth, g_vtth);

    unsigned short *wqh,*wkh,*wvh,*woh,*w1h,*w2h;
    cudaGetSymbolAddress((void**)&wqh, g_wqh);
    cudaGetSymbolAddress((void**)&wkh, g_wkh);
    cudaGetSymbolAddress((void**)&wvh, g_wvh);
    cudaGetSymbolAddress((void**)&woh, g_woh);
    cudaGetSymbolAddress((void**)&w1h, g_w1h);
    cudaGetSymbolAddress((void**)&w2h, g_w2h);

    cudaFuncSetAttribute(tgemm_kernel,  cudaFuncAttributeMaxDynamicSharedMemorySize, GEMM_SMEM);
    cudaFuncSetAttribute(attn_kernel,   cudaFuncAttributeMaxDynamicSharedMemorySize, AT_SMEM);

    dim3 gQ(DIMV/128, MROWS/128);       // (16, 32)
    dim3 gF(FFV/128, MROWS/128);        // (64, 32)

    // weight conversion + ln1
    wconv_kernel<<<dim3(DIMV/32, DIMV/32), 256>>>(wq, wqh, DIMV, DIMV);
    wconv_kernel<<<dim3(DIMV/32, DIMV/32), 256>>>(wk, wkh, DIMV, DIMV);
    wconv_kernel<<<dim3(DIMV/32, DIMV/32), 256>>>(wv, wvh, DIMV, DIMV);
    ln_kernel<<<MROWS, 256>>>(x, ln1w, ln1b, n_, ah);
    wconv_kernel<<<dim3(DIMV/32, DIMV/32), 256>>>(wo, woh, DIMV, DIMV);

    // QKV GEMMs (fp16-only outputs)
    tgemm_kernel<<<gQ, 256, GEMM_SMEM>>>(n_, ah, wqh, wq, nullptr, nullptr, q_, q16, MROWS, DIMV, DIMV, 0, 1, 0);
    tgemm_kernel<<<gQ, 256, GEMM_SMEM>>>(n_, ah, wkh, wk, nullptr, nullptr, k_, k16, MROWS, DIMV, DIMV, 0, 1, 0);
    tgemm_kernel<<<gQ, 256, GEMM_SMEM>>>(n_, ah, wvh, wv, nullptr, nullptr, v_, v16, MROWS, DIMV, DIMV, 0, 1, 0);

    // per-head LN + rotary + transpose
    qkrot_kernel<<<MROWS, 256>>>(q_, k_, v_, q16, k16, v16,
                                 nqw, nqb, nkw, nkb, fcos, fsin,
                                 qt_, kt_, vt_, qth, kth, vth);
    vtrans_kernel<<<dim3(SS/32, DHD/32, BB*HH), 256>>>(vth, vtth);

    // attention -> fp16 (ah)
    attn_kernel<<<dim3(SS/128, BB*HH), 256, AT_SMEM>>>(qt_, kt_, vt_,
                                                       qth, kth, vtth,
                                                       q_, ah);

    // FFN weight conversion
    wconv_kernel<<<dim3(FFV/32,  DIMV/32), 256>>>(w1, w1h, DIMV, FFV);
    wconv_kernel<<<dim3(DIMV/32, FFV/32),  256>>>(w2, w2h, FFV, DIMV);

    // x2 = x + attn @ wo + bo  (into g_k)
    tgemm_kernel<<<gQ, 256, GEMM_SMEM>>>(q_, ah, woh, wo, bo, x, k_, nullptr, MROWS, DIMV, DIMV, 3, 0, 1);

    // n2 = LN(x2) + fp16
    ln_kernel<<<MROWS, 256>>>(k_, ln3w, ln3b, n_, ah);

    // h = gelu(n2 @ w1 + b1): fp16-only output (128x128 tiles for 2-CTA occupancy)
    tgemm_kernel<<<gF, 256, GEMM_SMEM>>>(n_, ah, w1h, w1, b1, nullptr, h_, hh, MROWS, FFV, DIMV, 2, 1, 0);

    // out = x2 + h @ w2 + b2
    tgemm_kernel<<<gQ, 256, GEMM_SMEM>>>(h_, hh, w2h, w2, b2, k_, out, nullptr, MROWS, DIMV, FFV, 3, 0, 1);
}

// round 17
// speedup vs baseline: 1.0831x; 1.0831x over previous
#include <cuda_runtime.h>
#include <cuda_bf16.h>
#include <cuda_fp16.h>
#include <math.h>

// Problem constants
#define BB 2
#define SS 2048
#define DIMV 2048
#define HH 16
#define DHD 128
#define FFV 8192
#define MROWS (BB*SS)          // 4096

#if defined(__CUDA_ARCH_FEAT_SM103_ALL) || defined(__CUDA_ARCH_FEAT_SM100_ALL) || defined(__CUDA_ARCH_SPECIFIC__)
#define HAS_TCGEN05 1
#else
#define HAS_TCGEN05 0
#endif

// ---------------- scratch (device globals, no allocation) ----------------
__device__ float g_n [(size_t)MROWS*DIMV];
__device__ float g_q [(size_t)MROWS*DIMV];
__device__ float g_k [(size_t)MROWS*DIMV];
__device__ float g_v [(size_t)MROWS*DIMV];
__device__ float g_qt[(size_t)MROWS*DIMV];   // fallback fp32 q
__device__ float g_kt[(size_t)MROWS*DIMV];   // fallback fp32 k
__device__ float g_vt[(size_t)MROWS*DIMV];   // fallback fp32 v
__device__ float g_h [(size_t)MROWS*FFV];

// fp16 activations
__device__ unsigned short g_ah[(size_t)MROWS*DIMV];
__device__ unsigned short g_hh[(size_t)MROWS*FFV];   // also staging for fp16 q/k/v

// fp16 q/k/v for tensor attention  [b,h,s,dh]; v^T [b,h,dh,s]
__device__ unsigned short g_qth[(size_t)MROWS*DIMV];
__device__ unsigned short g_kth[(size_t)MROWS*DIMV];
__device__ unsigned short g_vth[(size_t)MROWS*DIMV];
__device__ unsigned short g_vtth[(size_t)MROWS*DIMV];

// fp16 transposed weights [N,K]
__device__ unsigned short g_wqh[(size_t)DIMV*DIMV];
__device__ unsigned short g_wkh[(size_t)DIMV*DIMV];
__device__ unsigned short g_wvh[(size_t)DIMV*DIMV];
__device__ unsigned short g_woh[(size_t)DIMV*DIMV];
__device__ unsigned short g_w1h[(size_t)DIMV*FFV];
__device__ unsigned short g_w2h[(size_t)DIMV*FFV];

// ---------------- f32x2 helpers (fallback paths) ----------------
__device__ __forceinline__ unsigned long long f2pack(float lo, float hi){
    unsigned long long r;
    asm("mov.b64 %0, {%1, %2};" : "=l"(r) : "f"(lo), "f"(hi));
    return r;
}
__device__ __forceinline__ unsigned long long f2dup(float x){
    unsigned long long r;
    asm("mov.b64 %0, {%1, %1};" : "=l"(r) : "f"(x));
    return r;
}
__device__ __forceinline__ unsigned long long f2fma(unsigned long long a, unsigned long long b, unsigned long long c){
    unsigned long long d;
    asm("fma.rn.f32x2 %0, %1, %2, %3;" : "=l"(d) : "l"(a), "l"(b), "l"(c));
    return d;
}
__device__ __forceinline__ unsigned long long f2mul(unsigned long long a, unsigned long long b){
    unsigned long long d;
    asm("mul.rn.f32x2 %0, %1, %2;" : "=l"(d) : "l"(a), "l"(b));
    return d;
}
__device__ __forceinline__ float2 f2unpack(unsigned long long v){
    float2 f;
    asm("mov.b64 {%0, %1}, %2;" : "=f"(f.x), "=f"(f.y) : "l"(v));
    return f;
}

// ---------------- fp16 pack helpers ----------------
__device__ __forceinline__ unsigned int cvt2h(float a, float b){
    __half2 h2 = __floats2half2_rn(a, b);
    return *(unsigned int*)&h2;
}
__device__ __forceinline__ void cvt_h_store(unsigned short* __restrict__ Ah,
                                            size_t idx, float4 v){
    uint2 hp;
    hp.x = cvt2h(v.x, v.y);
    hp.y = cvt2h(v.z, v.w);
    *(uint2*)(Ah + idx) = hp;
}
__device__ __forceinline__ void pack8_h(const float* v, uint4& hp){
    hp.x = cvt2h(v[0], v[1]);
    hp.y = cvt2h(v[2], v[3]);
    hp.z = cvt2h(v[4], v[5]);
    hp.w = cvt2h(v[6], v[7]);
}
__device__ __forceinline__ float4 ld_h4(const unsigned short* __restrict__ Ah, size_t idx){
    uint2 hp = *(const uint2*)(Ah + idx);
    __half2 a = *(__half2*)&hp.x;
    __half2 b = *(__half2*)&hp.y;
    float2 fa = __half22float2(a);
    float2 fb = __half22float2(b);
    return make_float4(fa.x, fa.y, fb.x, fb.y);
}

// ---------------- reductions ----------------
__device__ __forceinline__ float blockSum256(float v, float* sred){
    #pragma unroll
    for (int o=16;o>0;o>>=1) v += __shfl_xor_sync(0xffffffffu, v, o);
    __syncthreads();
    if ((threadIdx.x & 31)==0) sred[threadIdx.x>>5] = v;
    __syncthreads();
    float r = 0.f;
    #pragma unroll
    for (int i=0;i<8;i++) r += sred[i];
    return r;
}
__device__ __forceinline__ float warpSum(float v){
    #pragma unroll
    for (int o=16;o>0;o>>=1) v += __shfl_xor_sync(0xffffffffu, v, o);
    return v;
}

// ---------------- LayerNorm over DIM=2048 (+ fused fp16; fp32 out elided on tcgen05) ----------------
__global__ void __launch_bounds__(256) ln_kernel(const float* __restrict__ x,
                                                 const float* __restrict__ w,
                                                 const float* __restrict__ bia,
                                                 float* __restrict__ out,
                                                 unsigned short* __restrict__ Ah){
    __shared__ float sred[8];
    const int row = blockIdx.x;
    const int t = threadIdx.x;
    const float* xr = x + (size_t)row*DIMV;
    float4 a = *(const float4*)&xr[t*4];
    float4 b = *(const float4*)&xr[1024 + t*4];
    float s = a.x+a.y+a.z+a.w + b.x+b.y+b.z+b.w;
    s = blockSum256(s, sred);
    float mean = s * (1.f/2048.f);
    float d0=a.x-mean,d1=a.y-mean,d2=a.z-mean,d3=a.w-mean;
    float d4=b.x-mean,d5=b.y-mean,d6=b.z-mean,d7=b.w-mean;
    float sq = d0*d0+d1*d1+d2*d2+d3*d3+d4*d4+d5*d5+d6*d6+d7*d7;
    sq = blockSum256(sq, sred);
    float inv = rsqrtf(sq*(1.f/2048.f) + 1e-5f);
    float4 w0 = *(const float4*)&w[t*4];
    float4 w1 = *(const float4*)&w[1024 + t*4];
    float4 b0 = *(const float4*)&bia[t*4];
    float4 b1 = *(const float4*)&bia[1024 + t*4];
    float4 o0 = make_float4(d0*inv*w0.x+b0.x, d1*inv*w0.y+b0.y, d2*inv*w0.z+b0.z, d3*inv*w0.w+b0.w);
    float4 o1 = make_float4(d4*inv*w1.x+b1.x, d5*inv*w1.y+b1.y, d6*inv*w1.z+b1.z, d7*inv*w1.w+b1.w);
#if HAS_TCGEN05
    cvt_h_store(Ah, (size_t)row*DIMV + t*4, o0);
    cvt_h_store(Ah, (size_t)row*DIMV + 1024 + t*4, o1);
#else
    float* orow = out + (size_t)row*DIMV;
    *(float4*)&orow[t*4] = o0;
    *(float4*)&orow[1024 + t*4] = o1;
#endif
}

// ---------------- weight transpose + fp16 (8B stores) ----------------
__global__ void __launch_bounds__(256) wconv_kernel(const float* __restrict__ W,
                                                    unsigned short* __restrict__ Wh,
                                                    int K, int N){
#if HAS_TCGEN05
    __shared__ float sm[32][33];   // sm[k][n]
    const int n0 = blockIdx.x*32, k0 = blockIdx.y*32;
    const int tx = threadIdx.x & 31;
    const int ty = threadIdx.x >> 5;
    #pragma unroll
    for (int i=0;i<4;i++)
        sm[ty + i*8][tx] = W[(size_t)(k0 + ty + i*8)*N + n0 + tx];
    __syncthreads();
    // each thread: one output row nn, 4 consecutive k -> single 8B store
    const int nn = threadIdx.x >> 3;
    const int c  = (threadIdx.x & 7) * 4;
    uint2 hp;
    hp.x = cvt2h(sm[c+0][nn], sm[c+1][nn]);
    hp.y = cvt2h(sm[c+2][nn], sm[c+3][nn]);
    *(uint2*)(Wh + (size_t)(n0+nn)*K + k0 + c) = hp;
#endif
}

// ---------------- shared GEMM machinery ----------------
#define GBK 64
#define SW128(x) ((x) ^ (((x) >> 3) & 0x70))

static constexpr unsigned long long DESC_BASE =
    (2ull<<61) | (1ull<<46) | (64ull<<32) | (1ull<<16);   // SW128, ver1, SBO=64, LBO=1
__device__ __forceinline__ unsigned long long mkdesc(unsigned int addr){
    return DESC_BASE | ((unsigned long long)(addr >> 4) & 0x3FFFull);
}
#define IDESC_F16 ((1u<<4)|(16u<<17)|(8u<<24))   // M=128, N=128
#define IDESC_S16 ((1u<<4)|(8u<<17) |(8u<<24))   // M=128, N=64

__device__ __forceinline__ unsigned int smem_u32(const void* p){
    unsigned int a;
    asm("{ .reg .u64 t; cvta.to.shared.u64 t, %1; cvt.u32.u64 %0, t; }" : "=r"(a) : "l"(p));
    return a;
}

#if HAS_TCGEN05
__device__ __forceinline__ unsigned int elect1(){
    unsigned int p;
    asm volatile("{ .reg .pred P; elect.sync _|P, 0xffffffff; selp.b32 %0, 1, 0, P; }" : "=r"(p));
    return p;
}
__device__ __forceinline__ void mbar_init(unsigned int a, unsigned int cnt){
    asm volatile("mbarrier.init.shared.b64 [%0], %1;" :: "r"(a), "r"(cnt) : "memory");
}
__device__ __forceinline__ void mbar_wait(unsigned int a, unsigned int parity){
    asm volatile("{ .reg .pred P; WL_%=: mbarrier.try_wait.parity.shared.b64 P, [%0], %1; @!P bra WL_%=; }"
        :: "r"(a), "r"(parity) : "memory");
}
__device__ __forceinline__ void mma_f16_ss(unsigned int d, unsigned long long ad,
                                           unsigned long long bd, unsigned int idesc,
                                           unsigned int en){
    asm volatile("{\n\t.reg .pred p;\n\tsetp.ne.u32 p, %4, 0;\n\t"
        "tcgen05.mma.cta_group::1.kind::f16 [%0], %1, %2, %3, {%5,%5,%5,%5}, p;\n\t}"
        :: "r"(d), "l"(ad), "l"(bd), "r"(idesc), "r"(en), "r"(0u) : "memory");
}
__device__ __forceinline__ void tc_commit(unsigned int mbar){
    asm volatile("tcgen05.commit.cta_group::1.mbarrier::arrive::one.shared::cluster.b64 [%0];"
        :: "r"(mbar) : "memory");
}
// cp.async 16B (LDGSTS)
__device__ __forceinline__ void cp16(unsigned int dst, const void* src){
    asm volatile("cp.async.cg.shared.global [%0], [%1], 16;" :: "r"(dst), "l"(src) : "memory");
}
#define CP_COMMIT() asm volatile("cp.async.commit_group;" ::: "memory")
#define CP_WAIT0()  asm volatile("cp.async.wait_group 0;" ::: "memory")
#define CP_WAIT3()  asm volatile("cp.async.wait_group 3;" ::: "memory")
#define LDTM_X32(r, addr) \
    asm volatile("tcgen05.ld.sync.aligned.32x32b.x32.b32 " \
        "{%0, %1, %2, %3, %4, %5, %6, %7, %8, %9, %10, %11, %12, %13, %14, %15, " \
        " %16, %17, %18, %19, %20, %21, %22, %23, %24, %25, %26, %27, %28, %29, %30, %31}, [%32];" \
        : "=r"((r)[0]),  "=r"((r)[1]),  "=r"((r)[2]),  "=r"((r)[3]), \
          "=r"((r)[4]),  "=r"((r)[5]),  "=r"((r)[6]),  "=r"((r)[7]), \
          "=r"((r)[8]),  "=r"((r)[9]),  "=r"((r)[10]), "=r"((r)[11]), \
          "=r"((r)[12]), "=r"((r)[13]), "=r"((r)[14]), "=r"((r)[15]), \
          "=r"((r)[16]), "=r"((r)[17]), "=r"((r)[18]), "=r"((r)[19]), \
          "=r"((r)[20]), "=r"((r)[21]), "=r"((r)[22]), "=r"((r)[23]), \
          "=r"((r)[24]), "=r"((r)[25]), "=r"((r)[26]), "=r"((r)[27]), \
          "=r"((r)[28]), "=r"((r)[29]), "=r"((r)[30]), "=r"((r)[31]) \
        : "r"(addr))
#endif

// ---------------- tgemm: 128x128 tiles, 4-stage cp.async pipeline ----------------
#define NST 4
#define STAGE_BYTES 32768                 // Ah 16K | Bh 16K
#define SM_MBAR_OFF (NST*STAGE_BYTES)
#define SM_TPTR_OFF (SM_MBAR_OFF + 64)
#define GEMM_SMEM   (SM_TPTR_OFF + 64)

__global__ void __launch_bounds__(256) tgemm_kernel(const float* __restrict__ A,
        const unsigned short* __restrict__ Ah,
        const unsigned short* __restrict__ Bh,
        const float* __restrict__ Wf,
        const float* __restrict__ bias, const float* __restrict__ res,
        float* __restrict__ C,
        unsigned short* __restrict__ Cho,
        int M, int N, int K, int epi, int cvt, int wrC){
    extern __shared__ __align__(1024) char smem[];
    const int tid = threadIdx.x;
    const int n0 = blockIdx.x*128, m0 = blockIdx.y*128;

#if HAS_TCGEN05
    const unsigned int sb = smem_u32(smem);
    const int wid = tid >> 5, lid = tid & 31;

    if (wid == 0){
        asm volatile("tcgen05.alloc.cta_group::1.sync.aligned.shared::cta.b32 [%0], %1;"
            :: "r"(sb + SM_TPTR_OFF), "r"(128u) : "memory");
    }
    if (tid == 0){
        #pragma unroll
        for (int s=0;s<NST;s++) mbar_init(sb + SM_MBAR_OFF + s*8, 1);
    }
    __syncthreads();
    unsigned int tmem;
    asm volatile("ld.shared.b32 %0, [%1];" : "=r"(tmem) : "r"(sb + SM_TPTR_OFF));

    unsigned int pha[NST];
    #pragma unroll
    for (int s=0;s<NST;s++) pha[s]=0u;
    const int T = K / GBK;

    // prologue: tiles 0..2 -> stages 0..2 (one cp group per tile)
    #pragma unroll
    for (int p=0;p<3;p++){
        const unsigned int stp = sb + p*STAGE_BYTES;
        const int kp = p*GBK;
        #pragma unroll
        for (int i=0;i<4;i++){
            int ch = tid + i*256;
            int r = ch >> 3, cc = ch & 7;
            unsigned int sw = SW128((unsigned)(r*128 + cc*16));
            cp16(stp + 0     + sw, Ah + (size_t)(m0+r)*K + kp + cc*8);
            cp16(stp + 16384 + sw, Bh + (size_t)(n0+r)*K + kp + cc*8);
        }
        CP_COMMIT();
    }

    for (int t=0; t<T; t++){
        const int s = t & 3;
        const unsigned int stb = sb + s*STAGE_BYTES;
        if (t + 3 < T){
            const int ds = (t+3) & 3;      // stage for tile t+3 (== stage of tile t-1)
            if (t >= 1){
                mbar_wait(sb + SM_MBAR_OFF + ds*8, pha[ds]);
                pha[ds] ^= 1u;
            }
            const int k1 = (t+3)*GBK;
            const unsigned int stn = sb + ds*STAGE_BYTES;
            #pragma unroll
            for (int i=0;i<4;i++){
                int ch = tid + i*256;
                int r = ch >> 3, cc = ch & 7;
                unsigned int sw = SW128((unsigned)(r*128 + cc*16));
                cp16(stn + 0     + sw, Ah + (size_t)(m0+r)*K + k1 + cc*8);
                cp16(stn + 16384 + sw, Bh + (size_t)(n0+r)*K + k1 + cc*8);
            }
            CP_COMMIT();
            CP_WAIT3();          // tile t complete; t+1..t+3 in flight
        } else {
            CP_WAIT0();
        }
        asm volatile("fence.proxy.async.shared::cta;" ::: "memory");
        __syncthreads();
        if (wid == 0 && elect1()){
            unsigned long long dah = mkdesc(stb + 0);
            unsigned long long dbh = mkdesc(stb + 16384);
            unsigned int en0 = (t > 0) ? 1u : 0u;
            #pragma unroll
            for (int ks=0; ks<4; ks++)
                mma_f16_ss(tmem, dah + ks*2, dbh + ks*2, IDESC_F16, (ks==0)?en0:1u);
            tc_commit(sb + SM_MBAR_OFF + s*8);
        }
    }
    #pragma unroll
    for (int s=0;s<NST;s++) mbar_wait(sb + SM_MBAR_OFF + s*8, pha[s]);
    asm volatile("tcgen05.fence::after_thread_sync;" ::: "memory");

    if (wid < 4){
        const int m = m0 + wid*32 + lid;
        float* crow = C + (size_t)m*N + n0;
        #pragma unroll
        for (int c0=0; c0<128; c0+=32){
            unsigned int r[32];
            LDTM_X32(r, tmem + c0);
            asm volatile("tcgen05.wait::ld.sync.aligned;" ::: "memory");
            float vals[32];
            #pragma unroll
            for (int j=0;j<32;j++){
                float v = __uint_as_float(r[j]);
                int n = n0 + c0 + j;
                if (epi >= 1) v += bias[n];
                if (epi == 2) v = 0.5f * v * (1.0f + erff(v * 0.70710678118654752f));
                if (epi == 3) v += res[(size_t)m*N + n];
                vals[j] = v;
            }
            #pragma unroll
            for (int j=0;j<32;j+=4){
                float4 o4 = make_float4(vals[j],vals[j+1],vals[j+2],vals[j+3]);
                if (wrC) *(float4*)&crow[c0 + j] = o4;
                if (cvt) cvt_h_store(Cho, (size_t)m*N + n0 + c0 + j, o4);
            }
        }
    }
    __syncthreads();
    if (tid == 0){
        #pragma unroll
        for (int s=0;s<NST;s++)
            asm volatile("mbarrier.inval.shared.b64 [%0];" :: "r"(sb + SM_MBAR_OFF + s*8) : "memory");
    }
    __syncthreads();
    if (wid == 0){
        asm volatile("tcgen05.dealloc.cta_group::1.sync.aligned.b32 %0, %1;" :: "r"(tmem), "r"(128u));
    }

#else
    // fallback: fp32 SIMT f32x2 GEMM (R1-proven)
    float* As = (float*)smem;
    float* Bs = As + 16*128;
    const int tx = tid & 15;
    const int ty = tid >> 4;
    const float* Ab = A  + (size_t)m0*K;
    const float* Bb = Wf + n0;

    unsigned long long accp[8][4];
    #pragma unroll
    for (int i=0;i<8;i++)
        #pragma unroll
        for (int j=0;j<4;j++) accp[i][j] = 0ull;

    for (int k0=0; k0<K; k0+=16){
        #pragma unroll
        for (int l=0;l<2;l++){
            int f = tid + l*256;
            int r = f >> 2;
            int c4 = (f & 3) << 2;
            float4 v = *(const float4*)(Ab + (size_t)r*K + k0 + c4);
            As[(c4+0)*128+r]=v.x; As[(c4+1)*128+r]=v.y; As[(c4+2)*128+r]=v.z; As[(c4+3)*128+r]=v.w;
        }
        #pragma unroll
        for (int l=0;l<2;l++){
            int f = tid + l*256;
            int r = f >> 5;
            int c = (f & 31) << 2;
            *(float4*)(&Bs[r*128+c]) = *(const float4*)(Bb + (size_t)(k0+r)*N + c);
        }
        __syncthreads();
        #pragma unroll
        for (int kk=0;kk<16;kk++){
            float4 a0 = *(const float4*)(&As[kk*128 + ty*4]);
            float4 a1 = *(const float4*)(&As[kk*128 + ty*4+64]);
            float4 b0 = *(const float4*)(&Bs[kk*128 + tx*4]);
            float4 b1 = *(const float4*)(&Bs[kk*128 + tx*4+64]);
            unsigned long long bp0 = f2pack(b0.x,b0.y);
            unsigned long long bp1 = f2pack(b0.z,b0.w);
            unsigned long long bp2 = f2pack(b1.x,b1.y);
            unsigned long long bp3 = f2pack(b1.z,b1.w);
            float av[8] = {a0.x,a0.y,a0.z,a0.w,a1.x,a1.y,a1.z,a1.w};
            #pragma unroll
            for (int i=0;i<8;i++){
                unsigned long long ad = f2dup(av[i]);
                accp[i][0] = f2fma(ad, bp0, accp[i][0]);
                accp[i][1] = f2fma(ad, bp1, accp[i][1]);
                accp[i][2] = f2fma(ad, bp2, accp[i][2]);
                accp[i][3] = f2fma(ad, bp3, accp[i][3]);
            }
        }
        __syncthreads();
    }

    const int row0 = m0 + ty*4;
    const int col0 = n0 + tx*4;
    #pragma unroll
    for (int i=0;i<8;i++){
        int r = row0 + ((i<4) ? i : (60+i));
        float2 u0 = f2unpack(accp[i][0]);
        float2 u1 = f2unpack(accp[i][1]);
        float2 u2 = f2unpack(accp[i][2]);
        float2 u3 = f2unpack(accp[i][3]);
        float vals[8] = {u0.x,u0.y,u1.x,u1.y,u2.x,u2.y,u3.x,u3.y};
        float outv[8];
        #pragma unroll
        for (int jj=0;jj<8;jj++){
            int c = col0 + ((jj<4) ? jj : (60+jj));
            float v = vals[jj];
            if (epi >= 1) v += bias[c];
            if (epi == 2) v = 0.5f * v * (1.0f + erff(v * 0.70710678118654752f));
            if (epi == 3) v += res[(size_t)r*N + c];
            outv[jj] = v;
        }
        float* crow = C + (size_t)r*N;
        *(float4*)&crow[col0]      = make_float4(outv[0],outv[1],outv[2],outv[3]);
        *(float4*)&crow[col0 + 64] = make_float4(outv[4],outv[5],outv[6],outv[7]);
    }
#endif
}

// ---------------- tgemm2: 256x128 tiles (B reuse), 4-stage cp.async pipeline ----------------
#define STAGE2_BYTES 49152                // A0 16K | A1 16K | B 16K
#define SM2_MBAR_OFF (NST*STAGE2_BYTES)
#define SM2_TPTR_OFF (SM2_MBAR_OFF + 64)
#define GEMM2_SMEM   (SM2_TPTR_OFF + 64)

__global__ void __launch_bounds__(256) tgemm2_kernel(const float* __restrict__ A,
        const unsigned short* __restrict__ Ah,
        const unsigned short* __restrict__ Bh,
        const float* __restrict__ Wf,
        const float* __restrict__ bias, const float* __restrict__ res,
        float* __restrict__ C,
        unsigned short* __restrict__ Cho,
        int M, int N, int K, int epi, int cvt, int wrC){
    extern __shared__ __align__(1024) char smem[];
    const int tid = threadIdx.x;
    const int n0 = blockIdx.x*128, m0 = blockIdx.y*256;

#if HAS_TCGEN05
    const unsigned int sb = smem_u32(smem);
    const int wid = tid >> 5, lid = tid & 31;

    if (wid == 0){
        asm volatile("tcgen05.alloc.cta_group::1.sync.aligned.shared::cta.b32 [%0], %1;"
            :: "r"(sb + SM2_TPTR_OFF), "r"(256u) : "memory");
    }
    if (tid == 0){
        #pragma unroll
        for (int s=0;s<NST;s++) mbar_init(sb + SM2_MBAR_OFF + s*8, 1);
    }
    __syncthreads();
    unsigned int tmem;
    asm volatile("ld.shared.b32 %0, [%1];" : "=r"(tmem) : "r"(sb + SM2_TPTR_OFF));

    unsigned int pha[NST];
    #pragma unroll
    for (int s=0;s<NST;s++) pha[s]=0u;
    const int T = K / GBK;

    // prologue: tiles 0..2 -> stages 0..2
    #pragma unroll
    for (int p=0;p<3;p++){
        const unsigned int stp = sb + p*STAGE2_BYTES;
        const int kp = p*GBK;
        #pragma unroll
        for (int i=0;i<4;i++){
            int ch = tid + i*256;
            int r = ch >> 3, cc = ch & 7;
            unsigned int sw = SW128((unsigned)(r*128 + cc*16));
            cp16(stp + 0     + sw, Ah + (size_t)(m0+r)*K     + kp + cc*8);
            cp16(stp + 16384 + sw, Ah + (size_t)(m0+128+r)*K + kp + cc*8);
            cp16(stp + 32768 + sw, Bh + (size_t)(n0+r)*K     + kp + cc*8);
        }
        CP_COMMIT();
    }

    for (int t=0; t<T; t++){
        const int s = t & 3;
        const unsigned int stb = sb + s*STAGE2_BYTES;
        if (t + 3 < T){
            const int ds = (t+3) & 3;
            if (t >= 1){
                mbar_wait(sb + SM2_MBAR_OFF + ds*8, pha[ds]);
                pha[ds] ^= 1u;
            }
            const int k1 = (t+3)*GBK;
            const unsigned int stn = sb + ds*STAGE2_BYTES;
            #pragma unroll
            for (int i=0;i<4;i++){
                int ch = tid + i*256;
                int r = ch >> 3, cc = ch & 7;
                unsigned int sw = SW128((unsigned)(r*128 + cc*16));
                cp16(stn + 0     + sw, Ah + (size_t)(m0+r)*K     + k1 + cc*8);
                cp16(stn + 16384 + sw, Ah + (size_t)(m0+128+r)*K + k1 + cc*8);
                cp16(stn + 32768 + sw, Bh + (size_t)(n0+r)*K     + k1 + cc*8);
            }
            CP_COMMIT();
            CP_WAIT3();
        } else {
            CP_WAIT0();
        }
        asm volatile("fence.proxy.async.shared::cta;" ::: "memory");
        __syncthreads();
        if (wid == 0 && elect1()){
            unsigned long long da0 = mkdesc(stb + 0);
            unsigned long long da1 = mkdesc(stb + 16384);
            unsigned long long db  = mkdesc(stb + 32768);
            unsigned int en0 = (t > 0) ? 1u : 0u;
            #pragma unroll
            for (int ks=0; ks<4; ks++){
                unsigned int en = (ks==0) ? en0 : 1u;
                mma_f16_ss(tmem,       da0 + ks*2, db + ks*2, IDESC_F16, en);
                mma_f16_ss(tmem + 128, da1 + ks*2, db + ks*2, IDESC_F16, en);
            }
            tc_commit(sb + SM2_MBAR_OFF + s*8);
        }
    }
    #pragma unroll
    for (int s=0;s<NST;s++) mbar_wait(sb + SM2_MBAR_OFF + s*8, pha[s]);
    asm volatile("tcgen05.fence::after_thread_sync;" ::: "memory");

    {
        const int half = wid >> 2;
        const int m = m0 + half*128 + (wid & 3)*32 + lid;
        const unsigned int dbase = tmem + half*128;
        float* crow = C + (size_t)m*N + n0;
        #pragma unroll
        for (int c0=0; c0<128; c0+=32){
            unsigned int r[32];
            LDTM_X32(r, dbase + c0);
            asm volatile("tcgen05.wait::ld.sync.aligned;" ::: "memory");
            float vals[32];
            #pragma unroll
            for (int j=0;j<32;j++){
                float v = __uint_as_float(r[j]);
                int n = n0 + c0 + j;
                if (epi >= 1) v += bias[n];
                if (epi == 2) v = 0.5f * v * (1.0f + erff(v * 0.70710678118654752f));
                if (epi == 3) v += res[(size_t)m*N + n];
                vals[j] = v;
            }
            #pragma unroll
            for (int j=0;j<32;j+=4){
                float4 o4 = make_float4(vals[j],vals[j+1],vals[j+2],vals[j+3]);
                if (wrC) *(float4*)&crow[c0 + j] = o4;
                if (cvt) cvt_h_store(Cho, (size_t)m*N + n0 + c0 + j, o4);
            }
        }
    }
    __syncthreads();
    if (tid == 0){
        #pragma unroll
        for (int s=0;s<NST;s++)
            asm volatile("mbarrier.inval.shared.b64 [%0];" :: "r"(sb + SM2_MBAR_OFF + s*8) : "memory");
    }
    __syncthreads();
    if (wid == 0){
        asm volatile("tcgen05.dealloc.cta_group::1.sync.aligned.b32 %0, %1;" :: "r"(tmem), "r"(256u));
    }

#else
    // fallback: run the proven SIMT 128x128 GEMM twice (two M-halves)
    float* As = (float*)smem;
    float* Bs = As + 16*128;
    const int tx = tid & 15;
    const int ty = tid >> 4;
    for (int msub=0; msub<2; msub++){
        const int m0v = m0 + msub*128;
        const float* Ab = A  + (size_t)m0v*K;
        const float* Bb = Wf + n0;

        unsigned long long accp[8][4];
        #pragma unroll
        for (int i=0;i<8;i++)
            #pragma unroll
            for (int j=0;j<4;j++) accp[i][j] = 0ull;

        __syncthreads();
        for (int k0=0; k0<K; k0+=16){
            #pragma unroll
            for (int l=0;l<2;l++){
                int f = tid + l*256;
                int r = f >> 2;
                int c4 = (f & 3) << 2;
                float4 v = *(const float4*)(Ab + (size_t)r*K + k0 + c4);
                As[(c4+0)*128+r]=v.x; As[(c4+1)*128+r]=v.y; As[(c4+2)*128+r]=v.z; As[(c4+3)*128+r]=v.w;
            }
            #pragma unroll
            for (int l=0;l<2;l++){
                int f = tid + l*256;
                int r = f >> 5;
                int c = (f & 31) << 2;
                *(float4*)(&Bs[r*128+c]) = *(const float4*)(Bb + (size_t)(k0+r)*N + c);
            }
            __syncthreads();
            #pragma unroll
            for (int kk=0;kk<16;kk++){
                float4 a0 = *(const float4*)(&As[kk*128 + ty*4]);
                float4 a1 = *(const float4*)(&As[kk*128 + ty*4+64]);
                float4 b0 = *(const float4*)(&Bs[kk*128 + tx*4]);
                float4 b1 = *(const float4*)(&Bs[kk*128 + tx*4+64]);
                unsigned long long bp0 = f2pack(b0.x,b0.y);
                unsigned long long bp1 = f2pack(b0.z,b0.w);
                unsigned long long bp2 = f2pack(b1.x,b1.y);
                unsigned long long bp3 = f2pack(b1.z,b1.w);
                float av[8] = {a0.x,a0.y,a0.z,a0.w,a1.x,a1.y,a1.z,a1.w};
                #pragma unroll
                for (int i=0;i<8;i++){
                    unsigned long long ad = f2dup(av[i]);
                    accp[i][0] = f2fma(ad, bp0, accp[i][0]);
                    accp[i][1] = f2fma(ad, bp1, accp[i][1]);
                    accp[i][2] = f2fma(ad, bp2, accp[i][2]);
                    accp[i][3] = f2fma(ad, bp3, accp[i][3]);
                }
            }
            __syncthreads();
        }

        const int row0 = m0v + ty*4;
        const int col0 = n0 + tx*4;
        #pragma unroll
        for (int i=0;i<8;i++){
            int r = row0 + ((i<4) ? i : (60+i));
            float2 u0 = f2unpack(accp[i][0]);
            float2 u1 = f2unpack(accp[i][1]);
            float2 u2 = f2unpack(accp[i][2]);
            float2 u3 = f2unpack(accp[i][3]);
            float vals[8] = {u0.x,u0.y,u1.x,u1.y,u2.x,u2.y,u3.x,u3.y};
            float outv[8];
            #pragma unroll
            for (int jj=0;jj<8;jj++){
                int c = col0 + ((jj<4) ? jj : (60+jj));
                float v = vals[jj];
                if (epi >= 1) v += bias[c];
                if (epi == 2) v = 0.5f * v * (1.0f + erff(v * 0.70710678118654752f));
                if (epi == 3) v += res[(size_t)r*N + c];
                outv[jj] = v;
            }
            float* crow = C + (size_t)r*N;
            *(float4*)&crow[col0]      = make_float4(outv[0],outv[1],outv[2],outv[3]);
            *(float4*)&crow[col0 + 64] = make_float4(outv[4],outv[5],outv[6],outv[7]);
        }
    }
#endif
}

// ---------------- per-head LN + rotary + transpose ----------------
__global__ void __launch_bounds__(256) qkrot_kernel(const float* __restrict__ q,
                                                    const float* __restrict__ k,
                                                    const float* __restrict__ v,
                                                    const unsigned short* __restrict__ q16,
                                                    const unsigned short* __restrict__ k16,
                                                    const unsigned short* __restrict__ v16,
                                                    const float* __restrict__ nqw, const float* __restrict__ nqb,
                                                    const float* __restrict__ nkw, const float* __restrict__ nkb,
                                                    const float* __restrict__ fcos, const float* __restrict__ fsin,
                                                    float* __restrict__ qt, float* __restrict__ kt, float* __restrict__ vt,
                                                    unsigned short* __restrict__ qth,
                                                    unsigned short* __restrict__ kth,
                                                    unsigned short* __restrict__ vth){
    const int bs = blockIdx.x;
    const int b = bs >> 11;
    const int s = bs & (SS-1);
    const int wid = threadIdx.x >> 5;
    const int lane = threadIdx.x & 31;
    const int d0 = lane*4;
    const float c0 = fcos[s*64 + lane*2],     c1 = fcos[s*64 + lane*2 + 1];
    const float s0 = fsin[s*64 + lane*2],     s1 = fsin[s*64 + lane*2 + 1];
    const float4 wq4 = *(const float4*)&nqw[d0];
    const float4 bq4 = *(const float4*)&nqb[d0];
    const float4 wk4 = *(const float4*)&nkw[d0];
    const float4 bk4 = *(const float4*)&nkb[d0];
    const float scale = 0.08838834764831845f;
    #pragma unroll
    for (int hh = wid; hh < HH; hh += 8){
        size_t src = (size_t)bs*DIMV + hh*DHD + d0;
        size_t dst = ((size_t)(b*HH + hh)*SS + s)*DHD + d0;
        {
#if HAS_TCGEN05
            float4 xv = ld_h4(q16, src);
#else
            float4 xv = *(const float4*)&q[src];
#endif
            float mean = warpSum(xv.x+xv.y+xv.z+xv.w) * (1.f/128.f);
            float e0=xv.x-mean, e1=xv.y-mean, e2=xv.z-mean, e3=xv.w-mean;
            float var = warpSum(e0*e0+e1*e1+e2*e2+e3*e3) * (1.f/128.f);
            float inv = rsqrtf(var + 1e-5f);
            float y0 = e0*inv*wq4.x + bq4.x;
            float y1 = e1*inv*wq4.y + bq4.y;
            float y2 = e2*inv*wq4.z + bq4.z;
            float y3 = e3*inv*wq4.w + bq4.w;
            float4 r4 = make_float4(y0*c0 - y1*s0, y0*s0 + y1*c0,
                                    y2*c1 - y3*s1, y2*s1 + y3*c1);
#if HAS_TCGEN05
            float4 rs = make_float4(r4.x*scale, r4.y*scale, r4.z*scale, r4.w*scale);
            cvt_h_store(qth, dst, rs);
#else
            *(float4*)&qt[dst] = r4;
#endif
        }
        {
#if HAS_TCGEN05
            float4 xv = ld_h4(k16, src);
#else
            float4 xv = *(const float4*)&k[src];
#endif
            float mean = warpSum(xv.x+xv.y+xv.z+xv.w) * (1.f/128.f);
            float e0=xv.x-mean, e1=xv.y-mean, e2=xv.z-mean, e3=xv.w-mean;
            float var = warpSum(e0*e0+e1*e1+e2*e2+e3*e3) * (1.f/128.f);
            float inv = rsqrtf(var + 1e-5f);
            float y0 = e0*inv*wk4.x + bk4.x;
            float y1 = e1*inv*wk4.y + bk4.y;
            float y2 = e2*inv*wk4.z + bk4.z;
            float y3 = e3*inv*wk4.w + bk4.w;
            float4 r4 = make_float4(y0*c0 - y1*s0, y0*s0 + y1*c0,
                                    y2*c1 - y3*s1, y2*s1 + y3*c1);
#if HAS_TCGEN05
            cvt_h_store(kth, dst, r4);
#else
            *(float4*)&kt[dst] = r4;
#endif
        }
        {
#if HAS_TCGEN05
            uint2 hp = *(const uint2*)(v16 + src);
            *(uint2*)(vth + dst) = hp;
#else
            float4 xv = *(const float4*)&v[src];
            *(float4*)&vt[dst] = xv;
#endif
        }
    }
}

// ---------------- V transpose: [b,h,s,dh] -> [b,h,dh,s] ----------------
__global__ void __launch_bounds__(256) vtrans_kernel(const unsigned short* __restrict__ Vh,
                                                     unsigned short* __restrict__ Vth){
#if HAS_TCGEN05
    __shared__ unsigned short smh[32][33];
    const int s0 = blockIdx.x*32;
    const int d0 = blockIdx.y*32;
    const int bh = blockIdx.z;
    const int tx = threadIdx.x & 31;
    const int ty = threadIdx.x >> 5;
    const size_t inb  = (size_t)bh*SS*DHD + (size_t)s0*DHD + d0;
    const size_t outb = (size_t)bh*DHD*SS + (size_t)d0*SS + s0;
    #pragma unroll
    for (int i=0;i<4;i++){
        int r = ty + i*8;
        smh[r][tx] = Vh[inb + (size_t)r*DHD + tx];
    }
    __syncthreads();
    #pragma unroll
    for (int i=0;i<4;i++){
        int r = ty + i*8;
        Vth[outb + (size_t)r*SS + tx] = smh[tx][r];
    }
#endif
}

// ---------------- attention (fp16; double-buffered cp.async K/V) ----------------
#define AQ_H 0          // 32KB (2 dh-half blocks)
#define AK0  32768      // 16KB
#define AK1  49152
#define AV0  65536      // 16KB
#define AV1  81920
#define AP_H 98304      // 16KB
#define A_MBAR 114688
#define A_TPTR 114752
#define AT_SMEM 114816

__global__ void __launch_bounds__(256) attn_kernel(const float* __restrict__ Qf,
                                                   const float* __restrict__ Kf,
                                                   const float* __restrict__ Vf,
                                                   const unsigned short* __restrict__ Qh,
                                                   const unsigned short* __restrict__ Kh,
                                                   const unsigned short* __restrict__ Vth,
                                                   float* __restrict__ O,
                                                   unsigned short* __restrict__ Oh){
    extern __shared__ __align__(1024) char smem[];
#if HAS_TCGEN05
    const unsigned int sb = smem_u32(smem);
    const int tid = threadIdx.x;
    const int wid = tid >> 5, lid = tid & 31;
    const int q0 = blockIdx.x * 128;
    const int bh = blockIdx.y;
    const int b = bh >> 4, h = bh & 15;
    const size_t base  = (size_t)bh * SS * DHD;
    const size_t baseT = (size_t)bh * DHD * SS;
    const unsigned int AKo[2] = {AK0, AK1};
    const unsigned int AVo[2] = {AV0, AV1};

    if (wid == 0){
        asm volatile("tcgen05.alloc.cta_group::1.sync.aligned.shared::cta.b32 [%0], %1;"
            :: "r"(sb + A_TPTR), "r"(256u) : "memory");
    }
    if (tid == 0) mbar_init(sb + A_MBAR, 1);
    __syncthreads();
    unsigned int tmem;
    asm volatile("ld.shared.b32 %0, [%1];" : "=r"(tmem) : "r"(sb + A_TPTR));

    // Q tile (cp.async)
    #pragma unroll
    for (int i=0;i<8;i++){
        int ch = tid + i*256;
        int r = ch >> 4, c = ch & 15;
        int blk = c >> 3;
        unsigned int sw = blk*16384 + SW128((unsigned)(r*128 + (c&7)*16));
        cp16(sb + AQ_H + sw, Qh + base + (size_t)(q0+r)*DHD + c*8);
    }
    // prologue: K/V block 0 into buf0 (cp.async)
    #pragma unroll
    for (int i=0;i<4;i++){
        int ch = tid + i*256;
        int r = ch >> 4, c = ch & 15;
        int blk = c >> 3;
        unsigned int sw = blk*8192 + SW128((unsigned)(r*128 + (c&7)*16));
        cp16(sb + AK0 + sw, Kh + base + (size_t)r*DHD + c*8);
    }
    #pragma unroll
    for (int i=0;i<4;i++){
        int ch = tid + i*256;
        int r = ch >> 3, c = ch & 7;
        unsigned int sw = SW128((unsigned)(r*128 + c*16));
        cp16(sb + AV0 + sw, Vth + baseT + (size_t)r*SS + c*8);
    }
    CP_COMMIT();
    CP_WAIT0();
    asm volatile("fence.proxy.async.shared::cta;" ::: "memory");
    __syncthreads();

    float lsum = 0.f;
    unsigned int ph = 0u;
    const int NKB = SS/64;

    for (int kb = 0; kb < NKB; kb++){
        const int cur = kb & 1;
        const int nxt = cur ^ 1;

        // S = Q K^T from buf cur
        if (wid == 0 && elect1()){
            #pragma unroll
            for (int blk=0; blk<2; blk++){
                unsigned long long da = mkdesc(sb + AQ_H + blk*16384);
                unsigned long long db = mkdesc(sb + AKo[cur] + blk*8192);
                #pragma unroll
                for (int ks=0; ks<4; ks++){
                    unsigned int en = (blk==0 && ks==0) ? 0u : 1u;
                    mma_f16_ss(tmem, da + ks*2, db + ks*2, IDESC_S16, en);
                }
            }
            tc_commit(sb + A_MBAR);
        }

        // prefetch K/V block kb+1 into buf nxt (cp.async, overlaps S-MMA)
        if (kb + 1 < NKB){
            const int k1 = (kb+1)*64;
            #pragma unroll
            for (int i=0;i<4;i++){
                int ch = tid + i*256;
                int r = ch >> 4, c = ch & 15;
                int blk = c >> 3;
                unsigned int sw = blk*8192 + SW128((unsigned)(r*128 + (c&7)*16));
                cp16(sb + AKo[nxt] + sw, Kh + base + (size_t)(k1+r)*DHD + c*8);
            }
            #pragma unroll
            for (int i=0;i<4;i++){
                int ch = tid + i*256;
                int r = ch >> 3, c = ch & 7;
                unsigned int sw = SW128((unsigned)(r*128 + c*16));
                cp16(sb + AVo[nxt] + sw, Vth + baseT + (size_t)r*SS + k1 + c*8);
            }
            CP_COMMIT();
        }

        mbar_wait(sb + A_MBAR, ph); ph ^= 1u;
        asm volatile("tcgen05.fence::after_thread_sync;" ::: "memory");

        // softmax (no max-subtraction) + P fp16 store
        if (wid < 4){
            const int r = wid*32 + lid;
            #pragma unroll
            for (int c0=0; c0<64; c0+=32){
                unsigned int sr[32];
                LDTM_X32(sr, tmem + c0);
                asm volatile("tcgen05.wait::ld.sync.aligned;" ::: "memory");
                float pv[32];
                #pragma unroll
                for (int j=0;j<32;j++){
                    float e = __expf(fminf(__uint_as_float(sr[j]), 10.f));
                    pv[j] = e;
                    lsum += e;
                }
                #pragma unroll
                for (int j0=0;j0<32;j0+=8){
                    uint4 hp;
                    pack8_h(&pv[j0], hp);
                    unsigned int sw = SW128((unsigned)(r*128 + (c0+j0)*2));
                    *(uint4*)(smem + AP_H + sw) = hp;
                }
            }
        }
        // wait prefetch + fence + sync cover P stores AND nxt K/V
        CP_WAIT0();
        asm volatile("fence.proxy.async.shared::cta;" ::: "memory");
        __syncthreads();

        // O += P V from buf cur
        if (wid == 0 && elect1()){
            unsigned long long da = mkdesc(sb + AP_H);
            unsigned long long db = mkdesc(sb + AVo[cur]);
            #pragma unroll
            for (int ks=0; ks<4; ks++){
                unsigned int en = (kb==0 && ks==0) ? 0u : 1u;
                mma_f16_ss(tmem + 64, da + ks*2, db + ks*2, IDESC_F16, en);
            }
            tc_commit(sb + A_MBAR);
        }
        mbar_wait(sb + A_MBAR, ph); ph ^= 1u;
        asm volatile("tcgen05.fence::after_thread_sync;" ::: "memory");
    }

    // epilogue: normalize, write fp16 O
    if (wid < 4){
        const int r = wid*32 + lid;
        const float invl = 1.f / lsum;
        const size_t obase = (size_t)(b*SS + q0 + r)*DIMV + h*DHD;
        #pragma unroll
        for (int c0=0; c0<128; c0+=32){
            unsigned int orr[32];
            LDTM_X32(orr, tmem + 64 + c0);
            asm volatile("tcgen05.wait::ld.sync.aligned;" ::: "memory");
            #pragma unroll
            for (int j=0;j<32;j+=4){
                float4 o4 = make_float4(__uint_as_float(orr[j+0])*invl,
                                        __uint_as_float(orr[j+1])*invl,
                                        __uint_as_float(orr[j+2])*invl,
                                        __uint_as_float(orr[j+3])*invl);
                cvt_h_store(Oh, obase + c0 + j, o4);
            }
        }
    }
    __syncthreads();
    if (tid == 0){
        asm volatile("mbarrier.inval.shared.b64 [%0];" :: "r"(sb + A_MBAR) : "memory");
    }
    __syncthreads();
    if (wid == 0){
        asm volatile("tcgen05.dealloc.cta_group::1.sync.aligned.b32 %0, %1;" :: "r"(tmem), "r"(256u));
    }

#else
    // fallback: R5-proven SIMT attention, two 64-row halves
    float* smf = (float*)smem;
    #define QS_LD 68
    #define PS_LD 65
    float* Qs = smf;
    float* Ks = Qs + 128*QS_LD;
    float* Vs = Ks + 128*QS_LD;
    float* Ps = Vs + 64*128;
    const int bh = blockIdx.y;
    const int b = bh >> 4, h = bh & 15;
    const size_t base = (size_t)bh * SS * DHD;
    const int tid = threadIdx.x;
    const int tx = tid & 15;
    const int ty = tid >> 4;
    const float scale = 0.08838834764831845f;

    for (int qh = 0; qh < 2; qh++){
        const int q0 = blockIdx.x * 128 + qh*64;
        __syncthreads();
        for (int t=tid; t<64*128; t+=256){
            int r = t >> 7, d = t & 127;
            Qs[d*QS_LD + r] = Qf[base + (size_t)(q0+r)*DHD + d] * scale;
        }

        float m[4], l[4];
        unsigned long long o2[4][4];
        #pragma unroll
        for (int i=0;i<4;i++){
            m[i] = -1e30f; l[i] = 0.f;
            #pragma unroll
            for (int j=0;j<4;j++) o2[i][j] = 0ull;
        }

        for (int k0=0; k0<SS; k0+=64){
            __syncthreads();
            for (int t=tid; t<64*128; t+=256){
                int r = t >> 7, d = t & 127;
                Ks[d*QS_LD + r] = Kf[base + (size_t)(k0+r)*DHD + d];
                Vs[t]           = Vf[base + (size_t)(k0+r)*DHD + d];
            }
            __syncthreads();

            unsigned long long s2[4][2];
            #pragma unroll
            for (int i=0;i<4;i++){ s2[i][0]=0ull; s2[i][1]=0ull; }
            #pragma unroll 4
            for (int d=0; d<128; d++){
                float4 qv = *(const float4*)&Qs[d*QS_LD + ty*4];
                float4 kv = *(const float4*)&Ks[d*QS_LD + tx*4];
                unsigned long long kp0 = f2pack(kv.x,kv.y);
                unsigned long long kp1 = f2pack(kv.z,kv.w);
                float qa[4] = {qv.x,qv.y,qv.z,qv.w};
                #pragma unroll
                for (int i=0;i<4;i++){
                    unsigned long long qd = f2dup(qa[i]);
                    s2[i][0] = f2fma(qd, kp0, s2[i][0]);
                    s2[i][1] = f2fma(qd, kp1, s2[i][1]);
                }
            }

            #pragma unroll
            for (int i=0;i<4;i++){
                float2 sa = f2unpack(s2[i][0]);
                float2 sb2 = f2unpack(s2[i][1]);
                float sv0=sa.x, sv1=sa.y, sv2=sb2.x, sv3=sb2.y;
                float mt = fmaxf(fmaxf(sv0,sv1), fmaxf(sv2,sv3));
                #pragma unroll
                for (int o=1;o<16;o<<=1) mt = fmaxf(mt, __shfl_xor_sync(0xffffffffu, mt, o));
                float mnew = fmaxf(m[i], mt);
                float alpha = __expf(m[i] - mnew);
                float p0 = __expf(sv0 - mnew);
                float p1 = __expf(sv1 - mnew);
                float p2 = __expf(sv2 - mnew);
                float p3 = __expf(sv3 - mnew);
                float ssum = p0+p1+p2+p3;
                #pragma unroll
                for (int o=1;o<16;o<<=1) ssum += __shfl_xor_sync(0xffffffffu, ssum, o);
                l[i] = l[i]*alpha + ssum;
                m[i] = mnew;
                unsigned long long ad = f2dup(alpha);
                #pragma unroll
                for (int j=0;j<4;j++) o2[i][j] = f2mul(o2[i][j], ad);
                float* pr = &Ps[(ty*4+i)*PS_LD + tx*4];
                pr[0]=p0; pr[1]=p1; pr[2]=p2; pr[3]=p3;
            }
            __syncthreads();

            #pragma unroll 4
            for (int kk=0; kk<64; kk++){
                float4 v0 = *(const float4*)&Vs[kk*128 + tx*4];
                float4 v1 = *(const float4*)&Vs[kk*128 + 64 + tx*4];
                unsigned long long vp0 = f2pack(v0.x,v0.y);
                unsigned long long vp1 = f2pack(v0.z,v0.w);
                unsigned long long vp2 = f2pack(v1.x,v1.y);
                unsigned long long vp3 = f2pack(v1.z,v1.w);
                #pragma unroll
                for (int i=0;i<4;i++){
                    unsigned long long pd = f2dup(Ps[(ty*4+i)*PS_LD + kk]);
                    o2[i][0] = f2fma(pd, vp0, o2[i][0]);
                    o2[i][1] = f2fma(pd, vp1, o2[i][1]);
                    o2[i][2] = f2fma(pd, vp2, o2[i][2]);
                    o2[i][3] = f2fma(pd, vp3, o2[i][3]);
                }
            }
        }

        #pragma unroll
        for (int i=0;i<4;i++){
            float inv = 1.f / l[i];
            int r = q0 + ty*4 + i;
            size_t obase = (size_t)(b*SS + r)*DIMV + h*DHD;
            float2 p0 = f2unpack(o2[i][0]);
            float2 p1 = f2unpack(o2[i][1]);
            float2 p2 = f2unpack(o2[i][2]);
            float2 p3 = f2unpack(o2[i][3]);
            *(float4*)&O[obase + tx*4]      = make_float4(p0.x*inv, p0.y*inv, p1.x*inv, p1.y*inv);
            *(float4*)&O[obase + 64 + tx*4] = make_float4(p2.x*inv, p2.y*inv, p3.x*inv, p3.y*inv);
        }
    }
#endif
}

// ---------------- launch ----------------
extern "C" void kernel_launch(void* const* d_in, const int* in_sizes, int n_in,
                              void* d_out, int out_size){
    const float* x    = (const float*)d_in[0];
    const float* fcos = (const float*)d_in[1];
    const float* fsin = (const float*)d_in[2];
    const float* wq   = (const float*)d_in[3];
    const float* wk   = (const float*)d_in[4];
    const float* wv   = (const float*)d_in[5];
    const float* nqw  = (const float*)d_in[6];
    const float* nqb  = (const float*)d_in[7];
    const float* nkw  = (const float*)d_in[8];
    const float* nkb  = (const float*)d_in[9];
    const float* wo   = (const float*)d_in[10];
    const float* bo   = (const float*)d_in[11];
    const float* ln1w = (const float*)d_in[12];
    const float* ln1b = (const float*)d_in[13];
    const float* ln3w = (const float*)d_in[14];
    const float* ln3b = (const float*)d_in[15];
    const float* w1   = (const float*)d_in[16];
    const float* b1   = (const float*)d_in[17];
    const float* w2   = (const float*)d_in[18];
    const float* b2   = (const float*)d_in[19];
    float* out = (float*)d_out;

    float *n_, *q_, *k_, *v_, *qt_, *kt_, *vt_, *h_;
    cudaGetSymbolAddress((void**)&n_,  g_n);
    cudaGetSymbolAddress((void**)&q_,  g_q);
    cudaGetSymbolAddress((void**)&k_,  g_k);
    cudaGetSymbolAddress((void**)&v_,  g_v);
    cudaGetSymbolAddress((void**)&qt_, g_qt);
    cudaGetSymbolAddress((void**)&kt_, g_kt);
    cudaGetSymbolAddress((void**)&vt_, g_vt);
    cudaGetSymbolAddress((void**)&h_,  g_h);

    unsigned short *ah,*hh;
    cudaGetSymbolAddress((void**)&ah, g_ah);
    cudaGetSymbolAddress((void**)&hh, g_hh);
    unsigned short *q16 = hh;
    unsigned short *k16 = hh + (size_t)MROWS*DIMV;
    unsigned short *v16 = hh + 2*(size_t)MROWS*DIMV;

    unsigned short *qth,*kth,*vth,*vtth;
    cudaGetSymbolAddress((void**)&qth, g_qth);
    cudaGetSymbolAddress((void**)&kth, g_kth);
    cudaGetSymbolAddress((void**)&vth, g_vth);
    cudaGetSymbolAddress((void**)&vtth, g_vtth);

    unsigned short *wqh,*wkh,*wvh,*woh,*w1h,*w2h;
    cudaGetSymbolAddress((void**)&wqh, g_wqh);
    cudaGetSymbolAddress((void**)&wkh, g_wkh);
    cudaGetSymbolAddress((void**)&wvh, g_wvh);
    cudaGetSymbolAddress((void**)&woh, g_woh);
    cudaGetSymbolAddress((void**)&w1h, g_w1h);
    cudaGetSymbolAddress((void**)&w2h, g_w2h);

    cudaFuncSetAttribute(tgemm_kernel,  cudaFuncAttributeMaxDynamicSharedMemorySize, GEMM_SMEM);
    cudaFuncSetAttribute(tgemm2_kernel, cudaFuncAttributeMaxDynamicSharedMemorySize, GEMM2_SMEM);
    cudaFuncSetAttribute(attn_kernel,   cudaFuncAttributeMaxDynamicSharedMemorySize, AT_SMEM);

    dim3 gQ(DIMV/128, MROWS/128);       // (16, 32)
    dim3 gF2(FFV/128, MROWS/256);       // (64, 16) for tgemm2

    // weight conversion + ln1
    wconv_kernel<<<dim3(DIMV/32, DIMV/32), 256>>>(wq, wqh, DIMV, DIMV);
    wconv_kernel<<<dim3(DIMV/32, DIMV/32), 256>>>(wk, wkh, DIMV, DIMV);
    wconv_kernel<<<dim3(DIMV/32, DIMV/32), 256>>>(wv, wvh, DIMV, DIMV);
    ln_kernel<<<MROWS, 256>>>(x, ln1w, ln1b, n_, ah);
    wconv_kernel<<<dim3(DIMV/32, DIMV/32), 256>>>(wo, woh, DIMV, DIMV);

    // QKV GEMMs (fp16-only outputs)
    tgemm_kernel<<<gQ, 256, GEMM_SMEM>>>(n_, ah, wqh, wq, nullptr, nullptr, q_, q16, MROWS, DIMV, DIMV, 0, 1, 0);
    tgemm_kernel<<<gQ, 256, GEMM_SMEM>>>(n_, ah, wkh, wk, nullptr, nullptr, k_, k16, MROWS, DIMV, DIMV, 0, 1, 0);
    tgemm_kernel<<<gQ, 256, GEMM_SMEM>>>(n_, ah, wvh, wv, nullptr, nullptr, v_, v16, MROWS, DIMV, DIMV, 0, 1, 0);

    // per-head LN + rotary + transpose
    qkrot_kernel<<<MROWS, 256>>>(q_, k_, v_, q16, k16, v16,
                                 nqw, nqb, nkw, nkb, fcos, fsin,
                                 qt_, kt_, vt_, qth, kth, vth);
    vtrans_kernel<<<dim3(SS/32, DHD/32, BB*HH), 256>>>(vth, vtth);

    // attention -> fp16 (ah)
    attn_kernel<<<dim3(SS/128, BB*HH), 256, AT_SMEM>>>(qt_, kt_, vt_,
                                                       qth, kth, vtth,
                                                       q_, ah);

    // FFN weight conversion
    wconv_kernel<<<dim3(FFV/32,  DIMV/32), 256>>>(w1, w1h, DIMV, FFV);
    wconv_kernel<<<dim3(DIMV/32, FFV/32),  256>>>(w2, w2h, FFV, DIMV);

    // x2 = x + attn @ wo + bo  (into g_k)
    tgemm_kernel<<<gQ, 256, GEMM_SMEM>>>(q_, ah, woh, wo, bo, x, k_, nullptr, MROWS, DIMV, DIMV, 3, 0, 1);

    // n2 = LN(x2) + fp16
    ln_kernel<<<MROWS, 256>>>(k_, ln3w, ln3b, n_, ah);

    // h = gelu(n2 @ w1 + b1): M=256 tiles, fp16-only output
    tgemm2_kernel<<<gF2, 256, GEMM2_SMEM>>>(n_, ah, w1h, w1, b1, nullptr, h_, hh, MROWS, FFV, DIMV, 2, 1, 0);

    // out = x2 + h @ w2 + b2
    tgemm_kernel<<<gQ, 256, GEMM_SMEM>>>(h_, hh, w2h, w2, b2, k_, out, nullptr, MROWS, DIMV, FFV, 3, 0, 1);
}